// round 1
// baseline (speedup 1.0000x reference)
#include <cuda_runtime.h>
#include <cuda_bf16.h>
#include <math.h>

#define BL 2048      // BATCH*SEQ
#define SEQ 1024
#define DM 768
#define DI 1536
#define DTR 48
#define NS 16
#define XDBL 80      // DTR + 2*NS
#define VOCAB 50304

// ---------------- scratch (static device globals; no allocation) -------------
__device__ float g_X [BL * DM];        // residual stream
__device__ float g_Xn[BL * DM];        // rmsnorm output
__device__ float g_XZ[BL * 2 * DI];    // in_proj output (x | z)
__device__ float g_Xs[BL * DI];        // conv+silu(x)
__device__ float g_db[BL * XDBL];      // x_proj output (dt_in | B | C)
__device__ float g_dt[BL * DI];        // softplus(dt_proj)
__device__ float g_Y [BL * DI];        // scan output -> gated

// ---------------- helpers ----------------------------------------------------
__device__ __forceinline__ float siluf(float v) {
    return v / (1.f + __expf(-v));
}
__device__ __forceinline__ float softplusf(float v) {
    return v > 20.f ? v : log1pf(__expf(v));
}

// ---------------- embedding --------------------------------------------------
__global__ void embed_kernel(const int* __restrict__ tokens,
                             const float* __restrict__ wte,
                             float* __restrict__ X) {
    int t = blockIdx.x;
    int tok = tokens[t];
    const float4* src = (const float4*)(wte + (size_t)tok * DM);
    float4* dst = (float4*)(X + (size_t)t * DM);
    for (int i = threadIdx.x; i < DM / 4; i += blockDim.x) dst[i] = src[i];
}

// ---------------- rmsnorm (no weight) ----------------------------------------
__global__ void rmsnorm_kernel(const float* __restrict__ x,
                               float* __restrict__ o) {
    int t = blockIdx.x;
    const float* xr = x + (size_t)t * DM;
    float s = 0.f;
    for (int i = threadIdx.x; i < DM; i += blockDim.x) {
        float v = xr[i];
        s += v * v;
    }
#pragma unroll
    for (int off = 16; off; off >>= 1) s += __shfl_xor_sync(0xffffffffu, s, off);
    __shared__ float red[8];
    if ((threadIdx.x & 31) == 0) red[threadIdx.x >> 5] = s;
    __syncthreads();
    if (threadIdx.x < 32) {
        float v = (threadIdx.x < 8) ? red[threadIdx.x] : 0.f;
#pragma unroll
        for (int off = 4; off; off >>= 1) v += __shfl_xor_sync(0xffffffffu, v, off);
        if (threadIdx.x == 0) red[0] = v;
    }
    __syncthreads();
    float scale = rsqrtf(red[0] * (1.f / DM) + 1e-6f);
    float* orow = o + (size_t)t * DM;
    for (int i = threadIdx.x; i < DM; i += blockDim.x) orow[i] = xr[i] * scale;
}

// ---------------- generic TN SGEMM: C[M,N] = A[M,K] * B[N,K]^T (+addsrc) -----
// 128x128 tile, BK=16, 256 threads, 8x8 per thread.
// Requires: M % 128 == 0, K % 16 == 0. N arbitrary (bounds-checked).
__global__ __launch_bounds__(256) void sgemm_tn(
    const float* __restrict__ A, const float* __restrict__ B,
    const float* __restrict__ addsrc, float* __restrict__ C,
    int M, int N, int K) {
    __shared__ float sA[16][132];
    __shared__ float sB[16][132];
    const int tid = threadIdx.x;
    const int bm = blockIdx.y << 7;
    const int bn = blockIdx.x << 7;
    const int lr = tid >> 1;         // 0..127 : tile row being loaded
    const int lc = (tid & 1) << 3;   // 0 or 8 : k-offset within 16
    const int tx = tid & 15;         // n micro-tile index
    const int ty = tid >> 4;         // m micro-tile index

    float acc[8][8] = {};

    const float* Arow = A + (size_t)(bm + lr) * K + lc;
    const bool bok = (bn + lr) < N;
    const float* Brow = B + (size_t)(bok ? (bn + lr) : 0) * K + lc;

    for (int k0 = 0; k0 < K; k0 += 16) {
        float4 a0 = *(const float4*)(Arow + k0);
        float4 a1 = *(const float4*)(Arow + k0 + 4);
        float4 b0, b1;
        if (bok) {
            b0 = *(const float4*)(Brow + k0);
            b1 = *(const float4*)(Brow + k0 + 4);
        } else {
            b0 = make_float4(0.f, 0.f, 0.f, 0.f);
            b1 = b0;
        }
        sA[lc + 0][lr] = a0.x; sA[lc + 1][lr] = a0.y;
        sA[lc + 2][lr] = a0.z; sA[lc + 3][lr] = a0.w;
        sA[lc + 4][lr] = a1.x; sA[lc + 5][lr] = a1.y;
        sA[lc + 6][lr] = a1.z; sA[lc + 7][lr] = a1.w;
        sB[lc + 0][lr] = b0.x; sB[lc + 1][lr] = b0.y;
        sB[lc + 2][lr] = b0.z; sB[lc + 3][lr] = b0.w;
        sB[lc + 4][lr] = b1.x; sB[lc + 5][lr] = b1.y;
        sB[lc + 6][lr] = b1.z; sB[lc + 7][lr] = b1.w;
        __syncthreads();
#pragma unroll
        for (int k = 0; k < 16; k++) {
            float4 av0 = *(const float4*)&sA[k][ty << 2];
            float4 av1 = *(const float4*)&sA[k][64 + (ty << 2)];
            float4 bv0 = *(const float4*)&sB[k][tx << 2];
            float4 bv1 = *(const float4*)&sB[k][64 + (tx << 2)];
            float a[8] = {av0.x, av0.y, av0.z, av0.w, av1.x, av1.y, av1.z, av1.w};
            float b[8] = {bv0.x, bv0.y, bv0.z, bv0.w, bv1.x, bv1.y, bv1.z, bv1.w};
#pragma unroll
            for (int i = 0; i < 8; i++)
#pragma unroll
                for (int j = 0; j < 8; j++)
                    acc[i][j] = fmaf(a[i], b[j], acc[i][j]);
        }
        __syncthreads();
    }

#pragma unroll
    for (int i = 0; i < 8; i++) {
        int m = bm + ((i < 4) ? ((ty << 2) + i) : (64 + (ty << 2) + i - 4));
#pragma unroll
        for (int j = 0; j < 8; j++) {
            int n = bn + ((j < 4) ? ((tx << 2) + j) : (64 + (tx << 2) + j - 4));
            if (n < N) {
                size_t off = (size_t)m * N + n;
                float v = acc[i][j];
                if (addsrc) v += addsrc[off];
                C[off] = v;
            }
        }
    }
}

// ---------------- depthwise causal conv (width 4) + silu ---------------------
// x part lives at XZ[t*2*DI + d]; output g_Xs[t*DI + d]
__global__ void conv_silu_kernel(const float* __restrict__ XZ,
                                 const float* __restrict__ cw,
                                 const float* __restrict__ cb,
                                 float* __restrict__ out) {
    int idx = blockIdx.x * blockDim.x + threadIdx.x;
    if (idx >= BL * DI) return;
    int t = idx / DI, d = idx - t * DI;
    int l = t & (SEQ - 1);
    const float* w = cw + d * 4;
    float s = cb[d];
    s = fmaf(w[3], XZ[(size_t)t * (2 * DI) + d], s);
    if (l >= 1) s = fmaf(w[2], XZ[(size_t)(t - 1) * (2 * DI) + d], s);
    if (l >= 2) s = fmaf(w[1], XZ[(size_t)(t - 2) * (2 * DI) + d], s);
    if (l >= 3) s = fmaf(w[0], XZ[(size_t)(t - 3) * (2 * DI) + d], s);
    out[idx] = siluf(s);
}

// ---------------- dt_proj (K=48) + bias + softplus ----------------------------
__global__ void dtproj_kernel(const float* __restrict__ dbl,
                              const float* __restrict__ W,
                              const float* __restrict__ bias,
                              float* __restrict__ out) {
    int idx = blockIdx.x * blockDim.x + threadIdx.x;
    if (idx >= BL * DI) return;
    int t = idx / DI, d = idx - t * DI;
    const float4* a = (const float4*)(dbl + (size_t)t * XDBL);
    const float4* w = (const float4*)(W + (size_t)d * DTR);
    float s = bias[d];
#pragma unroll
    for (int r = 0; r < DTR / 4; r++) {
        float4 av = a[r], wv = w[r];
        s = fmaf(av.x, wv.x, s);
        s = fmaf(av.y, wv.y, s);
        s = fmaf(av.z, wv.z, s);
        s = fmaf(av.w, wv.w, s);
    }
    out[idx] = softplusf(s);
}

// ---------------- selective scan ----------------------------------------------
// 16 lanes per (b,d) channel, one state n per lane, sequential over L.
__global__ void scan_kernel(const float* __restrict__ dbl,
                            const float* __restrict__ dt,
                            const float* __restrict__ xs,
                            const float* __restrict__ A_log,
                            const float* __restrict__ Dvec,
                            float* __restrict__ y) {
    int gid = blockIdx.x * blockDim.x + threadIdx.x;
    int lane = threadIdx.x & 15;
    int ch = gid >> 4;
    if (ch >= 2 * DI) return;
    int b = ch / DI, d = ch - b * DI;
    float A = -expf(A_log[d * NS + lane]);
    float Dd = Dvec[d];
    float h = 0.f;
    const int tbase = b * SEQ;
    for (int l = 0; l < SEQ; l++) {
        int t = tbase + l;
        float dtv = dt[(size_t)t * DI + d];
        float xv = xs[(size_t)t * DI + d];
        float Bv = dbl[(size_t)t * XDBL + DTR + lane];
        float Cv = dbl[(size_t)t * XDBL + DTR + NS + lane];
        h = fmaf(__expf(dtv * A), h, dtv * Bv * xv);
        float p = h * Cv;
        p += __shfl_xor_sync(0xffffffffu, p, 8, 16);
        p += __shfl_xor_sync(0xffffffffu, p, 4, 16);
        p += __shfl_xor_sync(0xffffffffu, p, 2, 16);
        p += __shfl_xor_sync(0xffffffffu, p, 1, 16);
        if (lane == 0) y[(size_t)t * DI + d] = fmaf(Dd, xv, p);
    }
}

// ---------------- gate: y *= silu(z) -------------------------------------------
__global__ void gate_kernel(const float* __restrict__ XZ,
                            float* __restrict__ Y) {
    int idx = blockIdx.x * blockDim.x + threadIdx.x;
    if (idx >= BL * DI) return;
    int t = idx / DI, d = idx - t * DI;
    float z = XZ[(size_t)t * (2 * DI) + DI + d];
    Y[idx] *= siluf(z);
}

// ---------------- launch -------------------------------------------------------
extern "C" void kernel_launch(void* const* d_in, const int* in_sizes, int n_in,
                              void* d_out, int out_size) {
    const int*   tokens = (const int*)  d_in[0];
    const float* wte    = (const float*)d_in[1];
    const float* in_w   = (const float*)d_in[2];
    const float* conv_w = (const float*)d_in[3];
    const float* conv_b = (const float*)d_in[4];
    const float* xp_w   = (const float*)d_in[5];
    const float* dtp_w  = (const float*)d_in[6];
    const float* dtp_b  = (const float*)d_in[7];
    const float* out_w  = (const float*)d_in[8];
    const float* A_log  = (const float*)d_in[9];
    const float* Dvec   = (const float*)d_in[10];
    const float* lm_w   = (const float*)d_in[11];
    float* out = (float*)d_out;
    (void)in_sizes; (void)n_in; (void)out_size;

    float *X, *Xn, *XZ, *Xs, *db, *dtb, *Y;
    cudaGetSymbolAddress((void**)&X,  g_X);
    cudaGetSymbolAddress((void**)&Xn, g_Xn);
    cudaGetSymbolAddress((void**)&XZ, g_XZ);
    cudaGetSymbolAddress((void**)&Xs, g_Xs);
    cudaGetSymbolAddress((void**)&db, g_db);
    cudaGetSymbolAddress((void**)&dtb, g_dt);
    cudaGetSymbolAddress((void**)&Y,  g_Y);

    const int EW_BLOCKS = (BL * DI + 255) / 256;

    embed_kernel<<<BL, 256>>>(tokens, wte, X);

    for (int layer = 0; layer < 2; layer++) {
        const float* in_w_l   = in_w   + (size_t)layer * 2 * DI * DM;
        const float* conv_w_l = conv_w + (size_t)layer * DI * 4;
        const float* conv_b_l = conv_b + (size_t)layer * DI;
        const float* xp_w_l   = xp_w   + (size_t)layer * XDBL * DI;
        const float* dtp_w_l  = dtp_w  + (size_t)layer * DI * DTR;
        const float* dtp_b_l  = dtp_b  + (size_t)layer * DI;
        const float* out_w_l  = out_w  + (size_t)layer * DM * DI;
        const float* A_log_l  = A_log  + (size_t)layer * DI * NS;
        const float* D_l      = Dvec   + (size_t)layer * DI;

        rmsnorm_kernel<<<BL, 256>>>(X, Xn);
        sgemm_tn<<<dim3((2 * DI) / 128, BL / 128), 256>>>(
            Xn, in_w_l, nullptr, XZ, BL, 2 * DI, DM);
        conv_silu_kernel<<<EW_BLOCKS, 256>>>(XZ, conv_w_l, conv_b_l, Xs);
        sgemm_tn<<<dim3(1, BL / 128), 256>>>(
            Xs, xp_w_l, nullptr, db, BL, XDBL, DI);
        dtproj_kernel<<<EW_BLOCKS, 256>>>(db, dtp_w_l, dtp_b_l, dtb);
        scan_kernel<<<(2 * DI * NS) / 256, 256>>>(db, dtb, Xs, A_log_l, D_l, Y);
        gate_kernel<<<EW_BLOCKS, 256>>>(XZ, Y);
        sgemm_tn<<<dim3(DM / 128, BL / 128), 256>>>(
            Y, out_w_l, X, X, BL, DM, DI);
    }

    rmsnorm_kernel<<<BL, 256>>>(X, Xn);
    sgemm_tn<<<dim3(VOCAB / 128, BL / 128), 256>>>(
        Xn, lm_w, nullptr, out, BL, VOCAB, DM);
}

// round 4
// speedup vs baseline: 1.9214x; 1.9214x over previous
#include <cuda_runtime.h>
#include <cuda_bf16.h>
#include <math.h>
#include <stdint.h>

#define BL 2048      // BATCH*SEQ
#define SEQ 1024
#define DM 768
#define DI 1536
#define DTR 48
#define NS 16
#define XDBL 80      // DTR + 2*NS
#define VOCAB 50304

// ---------------- fp32 scratch ------------------------------------------------
__device__ float g_X [BL * DM];        // residual stream
__device__ float g_XZ[BL * 2 * DI];    // in_proj output (x | z)
__device__ float g_Xs[BL * DI];        // conv+silu(x) fp32 (for scan)
__device__ float g_db[BL * XDBL];      // x_proj output (dt_in | B | C)
__device__ float g_dt[BL * DI];        // softplus(dt_proj)
__device__ float g_Y [BL * DI];        // scan output

// ---------------- split-bf16 scratch -------------------------------------------
__device__ __nv_bfloat16 g_xnH[BL * DM],  g_xnL[BL * DM];    // rmsnorm out
__device__ __nv_bfloat16 g_xsH[BL * DI],  g_xsL[BL * DI];    // conv+silu out
__device__ __nv_bfloat16 g_ygH[BL * DI],  g_ygL[BL * DI];    // gated scan out
__device__ __nv_bfloat16 g_inwH[2 * 2 * DI * DM], g_inwL[2 * 2 * DI * DM];
__device__ __nv_bfloat16 g_xpwH[2 * XDBL * DI],   g_xpwL[2 * XDBL * DI];
__device__ __nv_bfloat16 g_otwH[2 * DM * DI],     g_otwL[2 * DM * DI];
__device__ __nv_bfloat16 g_lmwH[VOCAB * DM],      g_lmwL[VOCAB * DM];

// ---------------- helpers ----------------------------------------------------
__device__ __forceinline__ float siluf(float v) {
    return v / (1.f + __expf(-v));
}
__device__ __forceinline__ float softplusf(float v) {
    return v > 20.f ? v : log1pf(__expf(v));
}
__device__ __forceinline__ void split1(float v, __nv_bfloat16& h, __nv_bfloat16& l) {
    h = __float2bfloat16(v);
    l = __float2bfloat16(v - __bfloat162float(h));
}

// ---------------- fp32 -> (hi,lo) bf16 convert --------------------------------
__global__ void split_kernel(const float* __restrict__ x,
                             __nv_bfloat16* __restrict__ h,
                             __nv_bfloat16* __restrict__ l, int n4) {
    int i = blockIdx.x * blockDim.x + threadIdx.x;
    if (i >= n4) return;
    float4 v = ((const float4*)x)[i];
    __nv_bfloat16 h0, h1, h2, h3, l0, l1, l2, l3;
    split1(v.x, h0, l0); split1(v.y, h1, l1);
    split1(v.z, h2, l2); split1(v.w, h3, l3);
    ((__nv_bfloat162*)h)[i * 2 + 0] = __nv_bfloat162(h0, h1);
    ((__nv_bfloat162*)h)[i * 2 + 1] = __nv_bfloat162(h2, h3);
    ((__nv_bfloat162*)l)[i * 2 + 0] = __nv_bfloat162(l0, l1);
    ((__nv_bfloat162*)l)[i * 2 + 1] = __nv_bfloat162(l2, l3);
}

// ---------------- embedding --------------------------------------------------
__global__ void embed_kernel(const int* __restrict__ tokens,
                             const float* __restrict__ wte,
                             float* __restrict__ X) {
    int t = blockIdx.x;
    int tok = tokens[t];
    const float4* src = (const float4*)(wte + (size_t)tok * DM);
    float4* dst = (float4*)(X + (size_t)t * DM);
    for (int i = threadIdx.x; i < DM / 4; i += blockDim.x) dst[i] = src[i];
}

// ---------------- rmsnorm -> split bf16 ---------------------------------------
__global__ void rmsnorm_split_kernel(const float* __restrict__ x,
                                     __nv_bfloat16* __restrict__ oh,
                                     __nv_bfloat16* __restrict__ ol) {
    int t = blockIdx.x;
    const float* xr = x + (size_t)t * DM;
    float s = 0.f;
    for (int i = threadIdx.x; i < DM; i += blockDim.x) {
        float v = xr[i];
        s += v * v;
    }
#pragma unroll
    for (int off = 16; off; off >>= 1) s += __shfl_xor_sync(0xffffffffu, s, off);
    __shared__ float red[8];
    if ((threadIdx.x & 31) == 0) red[threadIdx.x >> 5] = s;
    __syncthreads();
    if (threadIdx.x < 32) {
        float v = (threadIdx.x < 8) ? red[threadIdx.x] : 0.f;
#pragma unroll
        for (int off = 4; off; off >>= 1) v += __shfl_xor_sync(0xffffffffu, v, off);
        if (threadIdx.x == 0) red[0] = v;
    }
    __syncthreads();
    float scale = rsqrtf(red[0] * (1.f / DM) + 1e-6f);
    for (int i = threadIdx.x; i < DM; i += blockDim.x) {
        __nv_bfloat16 h, l;
        split1(xr[i] * scale, h, l);
        oh[(size_t)t * DM + i] = h;
        ol[(size_t)t * DM + i] = l;
    }
}

// =============================================================================
// split-bf16 tensor-core TN GEMM:
//   C[M,N] = (Ah+Al)[M,K] * (Bh+Bl)[N,K]^T (+ optional fp32 addsrc)
// approximated as Ah*Bh + Ah*Bl + Al*Bh  (3x mma.m16n8k16.bf16)
// 128x128 block tile, BK=32, 3-stage cp.async pipeline, 8 warps.
// Warp tile 32(M) x 64(N). Requires M%128==0, K%32==0. N arbitrary.
// =============================================================================
#define BKH 32
#define SSTRH 40                       // bf16 elems per SMEM row (32 + 8 pad)
#define STG_E (128 * SSTRH)            // bf16 elems per matrix per stage
#define STG_B (STG_E * 2)              // bytes (10240)
#define SMEM_TOT (4 * 3 * STG_B)       // 4 matrices x 3 stages = 122880 B

__device__ __forceinline__ void cp_async16(unsigned dst, const void* src, int srcsize) {
    asm volatile("cp.async.cg.shared.global [%0], [%1], 16, %2;\n"
                 :: "r"(dst), "l"(src), "r"(srcsize));
}
__device__ __forceinline__ void cp_commit() {
    asm volatile("cp.async.commit_group;\n");
}
__device__ __forceinline__ void cp_wait1() {
    asm volatile("cp.async.wait_group 1;\n");
}

__device__ __forceinline__ void mma_bf16(float c[4], const unsigned a[4], const unsigned b[2]) {
    asm volatile(
        "mma.sync.aligned.m16n8k16.row.col.f32.bf16.bf16.f32 "
        "{%0,%1,%2,%3}, {%4,%5,%6,%7}, {%8,%9}, {%0,%1,%2,%3};\n"
        : "+f"(c[0]), "+f"(c[1]), "+f"(c[2]), "+f"(c[3])
        : "r"(a[0]), "r"(a[1]), "r"(a[2]), "r"(a[3]), "r"(b[0]), "r"(b[1]));
}

__global__ __launch_bounds__(256, 1) void mma_tn_bf16(
    const __nv_bfloat16* __restrict__ Ah, const __nv_bfloat16* __restrict__ Al,
    const __nv_bfloat16* __restrict__ Bh, const __nv_bfloat16* __restrict__ Bl,
    const float* __restrict__ addsrc, float* __restrict__ C,
    int M, int N, int K) {
    extern __shared__ __nv_bfloat16 sm[];
    // element-offset regions: [AH 3 stages][AL][BH][BL]
    __nv_bfloat16* AH = sm;
    __nv_bfloat16* AL = sm + 3 * STG_E;
    __nv_bfloat16* BH = sm + 6 * STG_E;
    __nv_bfloat16* BLs = sm + 9 * STG_E;

    const int tid  = threadIdx.x;
    const int bm   = blockIdx.y << 7;
    const int bn   = blockIdx.x << 7;
    const int warp = tid >> 5, lane = tid & 31;
    const int wm   = warp & 3;            // 0..3  (M subdiv, 32 rows)
    const int wn   = warp >> 2;           // 0..1  (N subdiv, 64 cols)
    const int g    = lane >> 2, tq = lane & 3;

    // loader: each thread does 2 rows x 1 16B-chunk per matrix per stage
    const int lrow = tid >> 2;            // 0..63
    const int lch  = tid & 3;             // 16B chunk (8 bf16)

    const unsigned sb  = (unsigned)__cvta_generic_to_shared(sm);
    const unsigned AHo = 0, ALo = 3 * STG_B, BHo = 6 * STG_B, BLo = 9 * STG_B;

    float acc[2][8][4];
#pragma unroll
    for (int i = 0; i < 2; i++)
#pragma unroll
        for (int j = 0; j < 8; j++)
#pragma unroll
            for (int q = 0; q < 4; q++) acc[i][j][q] = 0.f;

    const int KT = K / BKH;

    auto load_tile = [&](int s, int kt) {
        const int kb = kt * BKH + lch * 8;
#pragma unroll
        for (int r = 0; r < 2; r++) {
            int row = lrow + 64 * r;
            unsigned doff = (unsigned)((row * SSTRH + lch * 8) * 2 + s * STG_B);
            size_t agoff = (size_t)(bm + row) * K + kb;
            cp_async16(sb + AHo + doff, Ah + agoff, 16);
            cp_async16(sb + ALo + doff, Al + agoff, 16);
            int ok = (bn + row) < N;
            size_t bgoff = (size_t)(ok ? (bn + row) : 0) * K + kb;
            cp_async16(sb + BHo + doff, Bh + bgoff, ok ? 16 : 0);
            cp_async16(sb + BLo + doff, Bl + bgoff, ok ? 16 : 0);
        }
    };

#pragma unroll
    for (int s = 0; s < 2; s++) {
        if (s < KT) load_tile(s, s);
        cp_commit();
    }

    for (int kt = 0; kt < KT; kt++) {
        cp_wait1();
        __syncthreads();
        int nkt = kt + 2;
        if (nkt < KT) load_tile(nkt % 3, nkt);
        cp_commit();

        const __nv_bfloat16* aH = AH + (kt % 3) * STG_E;
        const __nv_bfloat16* aL = AL + (kt % 3) * STG_E;
        const __nv_bfloat16* bH = BH + (kt % 3) * STG_E;
        const __nv_bfloat16* bL = BLs + (kt % 3) * STG_E;

#pragma unroll
        for (int ks = 0; ks < 2; ks++) {
            const int k0 = ks * 16 + 2 * tq;
            unsigned ah[2][4], al[2][4];
#pragma unroll
            for (int mt = 0; mt < 2; mt++) {
                int r0 = wm * 32 + mt * 16 + g;
                ah[mt][0] = *(const unsigned*)(aH + (r0 * SSTRH + k0));
                ah[mt][1] = *(const unsigned*)(aH + ((r0 + 8) * SSTRH + k0));
                ah[mt][2] = *(const unsigned*)(aH + (r0 * SSTRH + k0 + 8));
                ah[mt][3] = *(const unsigned*)(aH + ((r0 + 8) * SSTRH + k0 + 8));
                al[mt][0] = *(const unsigned*)(aL + (r0 * SSTRH + k0));
                al[mt][1] = *(const unsigned*)(aL + ((r0 + 8) * SSTRH + k0));
                al[mt][2] = *(const unsigned*)(aL + (r0 * SSTRH + k0 + 8));
                al[mt][3] = *(const unsigned*)(aL + ((r0 + 8) * SSTRH + k0 + 8));
            }
            unsigned bh[8][2], bl[8][2];
#pragma unroll
            for (int nt = 0; nt < 8; nt++) {
                int n = wn * 64 + nt * 8 + g;
                bh[nt][0] = *(const unsigned*)(bH + (n * SSTRH + k0));
                bh[nt][1] = *(const unsigned*)(bH + (n * SSTRH + k0 + 8));
                bl[nt][0] = *(const unsigned*)(bL + (n * SSTRH + k0));
                bl[nt][1] = *(const unsigned*)(bL + (n * SSTRH + k0 + 8));
            }
#pragma unroll
            for (int mt = 0; mt < 2; mt++)
#pragma unroll
                for (int nt = 0; nt < 8; nt++) {
                    mma_bf16(acc[mt][nt], ah[mt], bh[nt]);
                    mma_bf16(acc[mt][nt], ah[mt], bl[nt]);
                    mma_bf16(acc[mt][nt], al[mt], bh[nt]);
                }
        }
        __syncthreads();
    }

    // ---- epilogue ----
#pragma unroll
    for (int mt = 0; mt < 2; mt++) {
        int row0 = bm + wm * 32 + mt * 16 + g;
#pragma unroll
        for (int nt = 0; nt < 8; nt++) {
            int col = bn + wn * 64 + nt * 8 + tq * 2;
            if (col + 1 < N) {
                size_t o0 = (size_t)row0 * N + col;
                size_t o1 = (size_t)(row0 + 8) * N + col;
                float2 v0 = make_float2(acc[mt][nt][0], acc[mt][nt][1]);
                float2 v1 = make_float2(acc[mt][nt][2], acc[mt][nt][3]);
                if (addsrc) {
                    const float2 r0 = *(const float2*)(addsrc + o0);
                    const float2 r1 = *(const float2*)(addsrc + o1);
                    v0.x += r0.x; v0.y += r0.y;
                    v1.x += r1.x; v1.y += r1.y;
                }
                *(float2*)(C + o0) = v0;
                *(float2*)(C + o1) = v1;
            } else if (col < N) {
                size_t o0 = (size_t)row0 * N + col;
                size_t o1 = (size_t)(row0 + 8) * N + col;
                float v0 = acc[mt][nt][0], v1 = acc[mt][nt][2];
                if (addsrc) { v0 += addsrc[o0]; v1 += addsrc[o1]; }
                C[o0] = v0;
                C[o1] = v1;
            }
        }
    }
}

// ---------------- depthwise causal conv (width 4) + silu, split out ----------
__global__ void conv_silu_kernel(const float* __restrict__ XZ,
                                 const float* __restrict__ cw,
                                 const float* __restrict__ cb,
                                 float* __restrict__ out,
                                 __nv_bfloat16* __restrict__ oh,
                                 __nv_bfloat16* __restrict__ ol) {
    int idx = blockIdx.x * blockDim.x + threadIdx.x;
    if (idx >= BL * DI) return;
    int t = idx / DI, d = idx - t * DI;
    int l = t & (SEQ - 1);
    const float* w = cw + d * 4;
    float s = cb[d];
    s = fmaf(w[3], XZ[(size_t)t * (2 * DI) + d], s);
    if (l >= 1) s = fmaf(w[2], XZ[(size_t)(t - 1) * (2 * DI) + d], s);
    if (l >= 2) s = fmaf(w[1], XZ[(size_t)(t - 2) * (2 * DI) + d], s);
    if (l >= 3) s = fmaf(w[0], XZ[(size_t)(t - 3) * (2 * DI) + d], s);
    float v = siluf(s);
    out[idx] = v;
    __nv_bfloat16 h, lo;
    split1(v, h, lo);
    oh[idx] = h;
    ol[idx] = lo;
}

// ---------------- dt_proj (K=48) + bias + softplus ----------------------------
__global__ void dtproj_kernel(const float* __restrict__ dbl,
                              const float* __restrict__ W,
                              const float* __restrict__ bias,
                              float* __restrict__ out) {
    int idx = blockIdx.x * blockDim.x + threadIdx.x;
    if (idx >= BL * DI) return;
    int t = idx / DI, d = idx - t * DI;
    const float4* a = (const float4*)(dbl + (size_t)t * XDBL);
    const float4* w = (const float4*)(W + (size_t)d * DTR);
    float s = bias[d];
#pragma unroll
    for (int r = 0; r < DTR / 4; r++) {
        float4 av = a[r], wv = w[r];
        s = fmaf(av.x, wv.x, s);
        s = fmaf(av.y, wv.y, s);
        s = fmaf(av.z, wv.z, s);
        s = fmaf(av.w, wv.w, s);
    }
    out[idx] = softplusf(s);
}

// ---------------- selective scan ----------------------------------------------
__global__ void scan_kernel(const float* __restrict__ dbl,
                            const float* __restrict__ dt,
                            const float* __restrict__ xs,
                            const float* __restrict__ A_log,
                            const float* __restrict__ Dvec,
                            float* __restrict__ y) {
    int gid = blockIdx.x * blockDim.x + threadIdx.x;
    int lane = threadIdx.x & 15;
    int ch = gid >> 4;
    if (ch >= 2 * DI) return;
    int b = ch / DI, d = ch - b * DI;
    float A = -expf(A_log[d * NS + lane]);
    float Dd = Dvec[d];
    float h = 0.f;
    const int tbase = b * SEQ;
    for (int l = 0; l < SEQ; l++) {
        int t = tbase + l;
        float dtv = dt[(size_t)t * DI + d];
        float xv = xs[(size_t)t * DI + d];
        float Bv = dbl[(size_t)t * XDBL + DTR + lane];
        float Cv = dbl[(size_t)t * XDBL + DTR + NS + lane];
        h = fmaf(__expf(dtv * A), h, dtv * Bv * xv);
        float p = h * Cv;
        p += __shfl_xor_sync(0xffffffffu, p, 8, 16);
        p += __shfl_xor_sync(0xffffffffu, p, 4, 16);
        p += __shfl_xor_sync(0xffffffffu, p, 2, 16);
        p += __shfl_xor_sync(0xffffffffu, p, 1, 16);
        if (lane == 0) y[(size_t)t * DI + d] = fmaf(Dd, xv, p);
    }
}

// ---------------- gate: yg = y * silu(z), split out ----------------------------
__global__ void gate_split_kernel(const float* __restrict__ XZ,
                                  const float* __restrict__ Y,
                                  __nv_bfloat16* __restrict__ oh,
                                  __nv_bfloat16* __restrict__ ol) {
    int idx = blockIdx.x * blockDim.x + threadIdx.x;
    if (idx >= BL * DI) return;
    int t = idx / DI, d = idx - t * DI;
    float z = XZ[(size_t)t * (2 * DI) + DI + d];
    float v = Y[idx] * siluf(z);
    __nv_bfloat16 h, lo;
    split1(v, h, lo);
    oh[idx] = h;
    ol[idx] = lo;
}

// ---------------- launch -------------------------------------------------------
extern "C" void kernel_launch(void* const* d_in, const int* in_sizes, int n_in,
                              void* d_out, int out_size) {
    const int*   tokens = (const int*)  d_in[0];
    const float* wte    = (const float*)d_in[1];
    const float* in_w   = (const float*)d_in[2];
    const float* conv_w = (const float*)d_in[3];
    const float* conv_b = (const float*)d_in[4];
    const float* xp_w   = (const float*)d_in[5];
    const float* dtp_w  = (const float*)d_in[6];
    const float* dtp_b  = (const float*)d_in[7];
    const float* out_w  = (const float*)d_in[8];
    const float* A_log  = (const float*)d_in[9];
    const float* Dvec   = (const float*)d_in[10];
    const float* lm_w   = (const float*)d_in[11];
    float* out = (float*)d_out;
    (void)in_sizes; (void)n_in; (void)out_size;

    float *X, *XZ, *Xs, *db, *dtb, *Y;
    cudaGetSymbolAddress((void**)&X,  g_X);
    cudaGetSymbolAddress((void**)&XZ, g_XZ);
    cudaGetSymbolAddress((void**)&Xs, g_Xs);
    cudaGetSymbolAddress((void**)&db, g_db);
    cudaGetSymbolAddress((void**)&dtb, g_dt);
    cudaGetSymbolAddress((void**)&Y,  g_Y);

    __nv_bfloat16 *xnH, *xnL, *xsH, *xsL, *ygH, *ygL;
    __nv_bfloat16 *inwH, *inwL, *xpwH, *xpwL, *otwH, *otwL, *lmwH, *lmwL;
    cudaGetSymbolAddress((void**)&xnH, g_xnH);
    cudaGetSymbolAddress((void**)&xnL, g_xnL);
    cudaGetSymbolAddress((void**)&xsH, g_xsH);
    cudaGetSymbolAddress((void**)&xsL, g_xsL);
    cudaGetSymbolAddress((void**)&ygH, g_ygH);
    cudaGetSymbolAddress((void**)&ygL, g_ygL);
    cudaGetSymbolAddress((void**)&inwH, g_inwH);
    cudaGetSymbolAddress((void**)&inwL, g_inwL);
    cudaGetSymbolAddress((void**)&xpwH, g_xpwH);
    cudaGetSymbolAddress((void**)&xpwL, g_xpwL);
    cudaGetSymbolAddress((void**)&otwH, g_otwH);
    cudaGetSymbolAddress((void**)&otwL, g_otwL);
    cudaGetSymbolAddress((void**)&lmwH, g_lmwH);
    cudaGetSymbolAddress((void**)&lmwL, g_lmwL);

    cudaFuncSetAttribute(mma_tn_bf16,
                         cudaFuncAttributeMaxDynamicSharedMemorySize, SMEM_TOT);

    // ---- split all weights to (hi,lo) bf16 ----
    auto split_launch = [&](const float* src, __nv_bfloat16* h, __nv_bfloat16* l, int n) {
        int n4 = n / 4;
        split_kernel<<<(n4 + 255) / 256, 256>>>(src, h, l, n4);
    };
    split_launch(in_w,  inwH, inwL, 2 * 2 * DI * DM);
    split_launch(xp_w,  xpwH, xpwL, 2 * XDBL * DI);
    split_launch(out_w, otwH, otwL, 2 * DM * DI);
    split_launch(lm_w,  lmwH, lmwL, VOCAB * DM);

    const int EW_BLOCKS = (BL * DI + 255) / 256;

    embed_kernel<<<BL, 256>>>(tokens, wte, X);

    for (int layer = 0; layer < 2; layer++) {
        size_t inw_off = (size_t)layer * 2 * DI * DM;
        size_t xpw_off = (size_t)layer * XDBL * DI;
        size_t otw_off = (size_t)layer * DM * DI;
        const float* conv_w_l = conv_w + (size_t)layer * DI * 4;
        const float* conv_b_l = conv_b + (size_t)layer * DI;
        const float* dtp_w_l  = dtp_w  + (size_t)layer * DI * DTR;
        const float* dtp_b_l  = dtp_b  + (size_t)layer * DI;
        const float* A_log_l  = A_log  + (size_t)layer * DI * NS;
        const float* D_l      = Dvec   + (size_t)layer * DI;

        rmsnorm_split_kernel<<<BL, 256>>>(X, xnH, xnL);
        mma_tn_bf16<<<dim3((2 * DI) / 128, BL / 128), 256, SMEM_TOT>>>(
            xnH, xnL, inwH + inw_off, inwL + inw_off, nullptr, XZ, BL, 2 * DI, DM);
        conv_silu_kernel<<<EW_BLOCKS, 256>>>(XZ, conv_w_l, conv_b_l, Xs, xsH, xsL);
        mma_tn_bf16<<<dim3(1, BL / 128), 256, SMEM_TOT>>>(
            xsH, xsL, xpwH + xpw_off, xpwL + xpw_off, nullptr, db, BL, XDBL, DI);
        dtproj_kernel<<<EW_BLOCKS, 256>>>(db, dtp_w_l, dtp_b_l, dtb);
        scan_kernel<<<(2 * DI * NS) / 256, 256>>>(db, dtb, Xs, A_log_l, D_l, Y);
        gate_split_kernel<<<EW_BLOCKS, 256>>>(XZ, Y, ygH, ygL);
        mma_tn_bf16<<<dim3(DM / 128, BL / 128), 256, SMEM_TOT>>>(
            ygH, ygL, otwH + otw_off, otwL + otw_off, X, X, BL, DM, DI);
    }

    rmsnorm_split_kernel<<<BL, 256>>>(X, xnH, xnL);
    mma_tn_bf16<<<dim3(VOCAB / 128, BL / 128), 256, SMEM_TOT>>>(
        xnH, xnL, lmwH, lmwL, nullptr, out, BL, VOCAB, DM);
}

// round 5
// speedup vs baseline: 1.9379x; 1.0086x over previous
#include <cuda_runtime.h>
#include <cuda_bf16.h>
#include <math.h>
#include <stdint.h>

#define BL 2048      // BATCH*SEQ
#define SEQ 1024
#define DM 768
#define DI 1536
#define DTR 48
#define NS 16
#define XDBL 80      // DTR + 2*NS
#define VOCAB 50304

// ---------------- fp32 scratch ------------------------------------------------
__device__ float g_X [BL * DM];        // residual stream
__device__ float g_XZ[BL * 2 * DI];    // in_proj output (x | z)
__device__ float g_Xs[BL * DI];        // conv+silu(x) fp32 (for scan)
__device__ float g_db[BL * XDBL];      // x_proj output (dt_in | B | C)
__device__ float g_dt[BL * DI];        // softplus(dt_proj)
__device__ float g_Y [BL * DI];        // scan output

// ---------------- split-bf16 scratch -------------------------------------------
__device__ __nv_bfloat16 g_xnH[BL * DM],  g_xnL[BL * DM];    // rmsnorm out
__device__ __nv_bfloat16 g_xsH[BL * DI],  g_xsL[BL * DI];    // conv+silu out
__device__ __nv_bfloat16 g_ygH[BL * DI],  g_ygL[BL * DI];    // gated scan out
__device__ __nv_bfloat16 g_inwH[2 * 2 * DI * DM], g_inwL[2 * 2 * DI * DM];
__device__ __nv_bfloat16 g_xpwH[2 * XDBL * DI],   g_xpwL[2 * XDBL * DI];
__device__ __nv_bfloat16 g_otwH[2 * DM * DI],     g_otwL[2 * DM * DI];
__device__ __nv_bfloat16 g_lmwH[VOCAB * DM],      g_lmwL[VOCAB * DM];

// ---------------- helpers ----------------------------------------------------
__device__ __forceinline__ float siluf(float v) {
    return v / (1.f + __expf(-v));
}
__device__ __forceinline__ float softplusf(float v) {
    return v > 20.f ? v : log1pf(__expf(v));
}
__device__ __forceinline__ void split1(float v, __nv_bfloat16& h, __nv_bfloat16& l) {
    h = __float2bfloat16(v);
    l = __float2bfloat16(v - __bfloat162float(h));
}

// ---------------- fp32 -> (hi,lo) bf16 convert --------------------------------
__global__ void split_kernel(const float* __restrict__ x,
                             __nv_bfloat16* __restrict__ h,
                             __nv_bfloat16* __restrict__ l, int n4) {
    int i = blockIdx.x * blockDim.x + threadIdx.x;
    if (i >= n4) return;
    float4 v = ((const float4*)x)[i];
    __nv_bfloat16 h0, h1, h2, h3, l0, l1, l2, l3;
    split1(v.x, h0, l0); split1(v.y, h1, l1);
    split1(v.z, h2, l2); split1(v.w, h3, l3);
    ((__nv_bfloat162*)h)[i * 2 + 0] = __nv_bfloat162(h0, h1);
    ((__nv_bfloat162*)h)[i * 2 + 1] = __nv_bfloat162(h2, h3);
    ((__nv_bfloat162*)l)[i * 2 + 0] = __nv_bfloat162(l0, l1);
    ((__nv_bfloat162*)l)[i * 2 + 1] = __nv_bfloat162(l2, l3);
}

// ---------------- embedding --------------------------------------------------
__global__ void embed_kernel(const int* __restrict__ tokens,
                             const float* __restrict__ wte,
                             float* __restrict__ X) {
    int t = blockIdx.x;
    int tok = tokens[t];
    const float4* src = (const float4*)(wte + (size_t)tok * DM);
    float4* dst = (float4*)(X + (size_t)t * DM);
    for (int i = threadIdx.x; i < DM / 4; i += blockDim.x) dst[i] = src[i];
}

// ---------------- rmsnorm -> split bf16 ---------------------------------------
__global__ void rmsnorm_split_kernel(const float* __restrict__ x,
                                     __nv_bfloat16* __restrict__ oh,
                                     __nv_bfloat16* __restrict__ ol) {
    int t = blockIdx.x;
    const float* xr = x + (size_t)t * DM;
    float s = 0.f;
    for (int i = threadIdx.x; i < DM; i += blockDim.x) {
        float v = xr[i];
        s += v * v;
    }
#pragma unroll
    for (int off = 16; off; off >>= 1) s += __shfl_xor_sync(0xffffffffu, s, off);
    __shared__ float red[8];
    if ((threadIdx.x & 31) == 0) red[threadIdx.x >> 5] = s;
    __syncthreads();
    if (threadIdx.x < 32) {
        float v = (threadIdx.x < 8) ? red[threadIdx.x] : 0.f;
#pragma unroll
        for (int off = 4; off; off >>= 1) v += __shfl_xor_sync(0xffffffffu, v, off);
        if (threadIdx.x == 0) red[0] = v;
    }
    __syncthreads();
    float scale = rsqrtf(red[0] * (1.f / DM) + 1e-6f);
    for (int i = threadIdx.x; i < DM; i += blockDim.x) {
        __nv_bfloat16 h, l;
        split1(xr[i] * scale, h, l);
        oh[(size_t)t * DM + i] = h;
        ol[(size_t)t * DM + i] = l;
    }
}

// =============================================================================
// split-bf16 tensor-core TN GEMM:
//   C[M,N] = (Ah+Al)[M,K] * (Bh+Bl)[N,K]^T (+ optional fp32 addsrc)
// approximated as Ah*Bh + Ah*Bl + Al*Bh  (3x mma.m16n8k16.bf16)
// 128x128 block tile, BK=32, 3-stage cp.async pipeline, 8 warps.
// Fragments loaded via ldmatrix.x4 (conflict-free with SSTRH=40).
// Grid: blockIdx.x = M block (fast; maximizes B-tile L2 reuse), blockIdx.y = N.
// Requires M%128==0, K%32==0. N arbitrary.
// =============================================================================
#define BKH 32
#define SSTRH 40                       // bf16 elems per SMEM row (32 + 8 pad)
#define STG_E (128 * SSTRH)            // bf16 elems per matrix per stage
#define STG_B (STG_E * 2)              // bytes (10240)
#define SMEM_TOT (4 * 3 * STG_B)       // 4 matrices x 3 stages = 122880 B

__device__ __forceinline__ void cp_async16(unsigned dst, const void* src, int srcsize) {
    asm volatile("cp.async.cg.shared.global [%0], [%1], 16, %2;\n"
                 :: "r"(dst), "l"(src), "r"(srcsize));
}
__device__ __forceinline__ void cp_commit() {
    asm volatile("cp.async.commit_group;\n");
}
__device__ __forceinline__ void cp_wait1() {
    asm volatile("cp.async.wait_group 1;\n");
}
__device__ __forceinline__ void ldsm_x4(unsigned r[4], unsigned addr) {
    asm volatile("ldmatrix.sync.aligned.m8n8.x4.shared.b16 {%0,%1,%2,%3}, [%4];"
                 : "=r"(r[0]), "=r"(r[1]), "=r"(r[2]), "=r"(r[3]) : "r"(addr));
}

__device__ __forceinline__ void mma_bf16(float c[4], const unsigned a[4], const unsigned b[2]) {
    asm volatile(
        "mma.sync.aligned.m16n8k16.row.col.f32.bf16.bf16.f32 "
        "{%0,%1,%2,%3}, {%4,%5,%6,%7}, {%8,%9}, {%0,%1,%2,%3};\n"
        : "+f"(c[0]), "+f"(c[1]), "+f"(c[2]), "+f"(c[3])
        : "r"(a[0]), "r"(a[1]), "r"(a[2]), "r"(a[3]), "r"(b[0]), "r"(b[1]));
}

__global__ __launch_bounds__(256, 1) void mma_tn_bf16(
    const __nv_bfloat16* __restrict__ Ah, const __nv_bfloat16* __restrict__ Al,
    const __nv_bfloat16* __restrict__ Bh, const __nv_bfloat16* __restrict__ Bl,
    const float* __restrict__ addsrc, float* __restrict__ C,
    int M, int N, int K) {
    extern __shared__ __nv_bfloat16 sm[];

    const int tid  = threadIdx.x;
    const int bm   = blockIdx.x << 7;   // M fast -> B tiles reused across wave
    const int bn   = blockIdx.y << 7;
    const int warp = tid >> 5, lane = tid & 31;
    const int wm   = warp & 3;            // 0..3  (M subdiv, 32 rows)
    const int wn   = warp >> 2;           // 0..1  (N subdiv, 64 cols)
    const int g    = lane >> 2, tq = lane & 3;

    // ldmatrix lane->address mapping (element offsets within tile)
    const int a_row = (lane & 7) + 8 * ((lane >> 3) & 1);  // 0..15
    const int a_col = 8 * (lane >> 4);                     // 0 or 8
    const int b_row = (lane & 7) + 8 * (lane >> 4);        // 0..15
    const int b_col = 8 * ((lane >> 3) & 1);               // 0 or 8

    // loader: each thread does 2 rows x 1 16B-chunk per matrix per stage
    const int lrow = tid >> 2;            // 0..63
    const int lch  = tid & 3;             // 16B chunk (8 bf16)

    const unsigned sb  = (unsigned)__cvta_generic_to_shared(sm);
    const unsigned AHo = 0, ALo = 3 * STG_B, BHo = 6 * STG_B, BLo = 9 * STG_B;

    float acc[2][8][4];
#pragma unroll
    for (int i = 0; i < 2; i++)
#pragma unroll
        for (int j = 0; j < 8; j++)
#pragma unroll
            for (int q = 0; q < 4; q++) acc[i][j][q] = 0.f;

    const int KT = K / BKH;

    auto load_tile = [&](int s, int kt) {
        const int kb = kt * BKH + lch * 8;
#pragma unroll
        for (int r = 0; r < 2; r++) {
            int row = lrow + 64 * r;
            unsigned doff = (unsigned)((row * SSTRH + lch * 8) * 2 + s * STG_B);
            size_t agoff = (size_t)(bm + row) * K + kb;
            cp_async16(sb + AHo + doff, Ah + agoff, 16);
            cp_async16(sb + ALo + doff, Al + agoff, 16);
            int ok = (bn + row) < N;
            size_t bgoff = (size_t)(ok ? (bn + row) : 0) * K + kb;
            cp_async16(sb + BHo + doff, Bh + bgoff, ok ? 16 : 0);
            cp_async16(sb + BLo + doff, Bl + bgoff, ok ? 16 : 0);
        }
    };

#pragma unroll
    for (int s = 0; s < 2; s++) {
        if (s < KT) load_tile(s, s);
        cp_commit();
    }

    for (int kt = 0; kt < KT; kt++) {
        cp_wait1();
        __syncthreads();
        int nkt = kt + 2;
        if (nkt < KT) load_tile(nkt % 3, nkt);
        cp_commit();

        const unsigned stoff = (unsigned)((kt % 3) * STG_B);

#pragma unroll
        for (int ks = 0; ks < 2; ks++) {
            unsigned ah[2][4], al[2][4];
#pragma unroll
            for (int mt = 0; mt < 2; mt++) {
                unsigned off = (unsigned)(((wm * 32 + mt * 16 + a_row) * SSTRH
                                           + ks * 16 + a_col) * 2);
                ldsm_x4(ah[mt], sb + AHo + stoff + off);
                ldsm_x4(al[mt], sb + ALo + stoff + off);
            }
            unsigned bh[8][2], bl[8][2];
#pragma unroll
            for (int grp = 0; grp < 4; grp++) {
                unsigned off = (unsigned)(((wn * 64 + grp * 16 + b_row) * SSTRH
                                           + ks * 16 + b_col) * 2);
                unsigned t[4];
                ldsm_x4(t, sb + BHo + stoff + off);
                bh[grp * 2][0] = t[0]; bh[grp * 2][1] = t[1];
                bh[grp * 2 + 1][0] = t[2]; bh[grp * 2 + 1][1] = t[3];
                ldsm_x4(t, sb + BLo + stoff + off);
                bl[grp * 2][0] = t[0]; bl[grp * 2][1] = t[1];
                bl[grp * 2 + 1][0] = t[2]; bl[grp * 2 + 1][1] = t[3];
            }
#pragma unroll
            for (int mt = 0; mt < 2; mt++)
#pragma unroll
                for (int nt = 0; nt < 8; nt++) {
                    mma_bf16(acc[mt][nt], ah[mt], bh[nt]);
                    mma_bf16(acc[mt][nt], ah[mt], bl[nt]);
                    mma_bf16(acc[mt][nt], al[mt], bh[nt]);
                }
        }
        __syncthreads();
    }

    // ---- epilogue ----
#pragma unroll
    for (int mt = 0; mt < 2; mt++) {
        int row0 = bm + wm * 32 + mt * 16 + g;
#pragma unroll
        for (int nt = 0; nt < 8; nt++) {
            int col = bn + wn * 64 + nt * 8 + tq * 2;
            if (col + 1 < N) {
                size_t o0 = (size_t)row0 * N + col;
                size_t o1 = (size_t)(row0 + 8) * N + col;
                float2 v0 = make_float2(acc[mt][nt][0], acc[mt][nt][1]);
                float2 v1 = make_float2(acc[mt][nt][2], acc[mt][nt][3]);
                if (addsrc) {
                    const float2 r0 = *(const float2*)(addsrc + o0);
                    const float2 r1 = *(const float2*)(addsrc + o1);
                    v0.x += r0.x; v0.y += r0.y;
                    v1.x += r1.x; v1.y += r1.y;
                }
                *(float2*)(C + o0) = v0;
                *(float2*)(C + o1) = v1;
            } else if (col < N) {
                size_t o0 = (size_t)row0 * N + col;
                size_t o1 = (size_t)(row0 + 8) * N + col;
                float v0 = acc[mt][nt][0], v1 = acc[mt][nt][2];
                if (addsrc) { v0 += addsrc[o0]; v1 += addsrc[o1]; }
                C[o0] = v0;
                C[o1] = v1;
            }
        }
    }
}

// ---------------- depthwise causal conv (width 4) + silu, split out ----------
__global__ void conv_silu_kernel(const float* __restrict__ XZ,
                                 const float* __restrict__ cw,
                                 const float* __restrict__ cb,
                                 float* __restrict__ out,
                                 __nv_bfloat16* __restrict__ oh,
                                 __nv_bfloat16* __restrict__ ol) {
    int idx = blockIdx.x * blockDim.x + threadIdx.x;
    if (idx >= BL * DI) return;
    int t = idx / DI, d = idx - t * DI;
    int l = t & (SEQ - 1);
    const float* w = cw + d * 4;
    float s = cb[d];
    s = fmaf(w[3], XZ[(size_t)t * (2 * DI) + d], s);
    if (l >= 1) s = fmaf(w[2], XZ[(size_t)(t - 1) * (2 * DI) + d], s);
    if (l >= 2) s = fmaf(w[1], XZ[(size_t)(t - 2) * (2 * DI) + d], s);
    if (l >= 3) s = fmaf(w[0], XZ[(size_t)(t - 3) * (2 * DI) + d], s);
    float v = siluf(s);
    out[idx] = v;
    __nv_bfloat16 h, lo;
    split1(v, h, lo);
    oh[idx] = h;
    ol[idx] = lo;
}

// ---------------- dt_proj (K=48) + bias + softplus ----------------------------
__global__ void dtproj_kernel(const float* __restrict__ dbl,
                              const float* __restrict__ W,
                              const float* __restrict__ bias,
                              float* __restrict__ out) {
    int idx = blockIdx.x * blockDim.x + threadIdx.x;
    if (idx >= BL * DI) return;
    int t = idx / DI, d = idx - t * DI;
    const float4* a = (const float4*)(dbl + (size_t)t * XDBL);
    const float4* w = (const float4*)(W + (size_t)d * DTR);
    float s = bias[d];
#pragma unroll
    for (int r = 0; r < DTR / 4; r++) {
        float4 av = a[r], wv = w[r];
        s = fmaf(av.x, wv.x, s);
        s = fmaf(av.y, wv.y, s);
        s = fmaf(av.z, wv.z, s);
        s = fmaf(av.w, wv.w, s);
    }
    out[idx] = softplusf(s);
}

// ---------------- selective scan ----------------------------------------------
__global__ void scan_kernel(const float* __restrict__ dbl,
                            const float* __restrict__ dt,
                            const float* __restrict__ xs,
                            const float* __restrict__ A_log,
                            const float* __restrict__ Dvec,
                            float* __restrict__ y) {
    int gid = blockIdx.x * blockDim.x + threadIdx.x;
    int lane = threadIdx.x & 15;
    int ch = gid >> 4;
    if (ch >= 2 * DI) return;
    int b = ch / DI, d = ch - b * DI;
    float A = -expf(A_log[d * NS + lane]);
    float Dd = Dvec[d];
    float h = 0.f;
    const int tbase = b * SEQ;
    for (int l = 0; l < SEQ; l++) {
        int t = tbase + l;
        float dtv = dt[(size_t)t * DI + d];
        float xv = xs[(size_t)t * DI + d];
        float Bv = dbl[(size_t)t * XDBL + DTR + lane];
        float Cv = dbl[(size_t)t * XDBL + DTR + NS + lane];
        h = fmaf(__expf(dtv * A), h, dtv * Bv * xv);
        float p = h * Cv;
        p += __shfl_xor_sync(0xffffffffu, p, 8, 16);
        p += __shfl_xor_sync(0xffffffffu, p, 4, 16);
        p += __shfl_xor_sync(0xffffffffu, p, 2, 16);
        p += __shfl_xor_sync(0xffffffffu, p, 1, 16);
        if (lane == 0) y[(size_t)t * DI + d] = fmaf(Dd, xv, p);
    }
}

// ---------------- gate: yg = y * silu(z), split out ----------------------------
__global__ void gate_split_kernel(const float* __restrict__ XZ,
                                  const float* __restrict__ Y,
                                  __nv_bfloat16* __restrict__ oh,
                                  __nv_bfloat16* __restrict__ ol) {
    int idx = blockIdx.x * blockDim.x + threadIdx.x;
    if (idx >= BL * DI) return;
    int t = idx / DI, d = idx - t * DI;
    float z = XZ[(size_t)t * (2 * DI) + DI + d];
    float v = Y[idx] * siluf(z);
    __nv_bfloat16 h, lo;
    split1(v, h, lo);
    oh[idx] = h;
    ol[idx] = lo;
}

// ---------------- launch -------------------------------------------------------
extern "C" void kernel_launch(void* const* d_in, const int* in_sizes, int n_in,
                              void* d_out, int out_size) {
    const int*   tokens = (const int*)  d_in[0];
    const float* wte    = (const float*)d_in[1];
    const float* in_w   = (const float*)d_in[2];
    const float* conv_w = (const float*)d_in[3];
    const float* conv_b = (const float*)d_in[4];
    const float* xp_w   = (const float*)d_in[5];
    const float* dtp_w  = (const float*)d_in[6];
    const float* dtp_b  = (const float*)d_in[7];
    const float* out_w  = (const float*)d_in[8];
    const float* A_log  = (const float*)d_in[9];
    const float* Dvec   = (const float*)d_in[10];
    const float* lm_w   = (const float*)d_in[11];
    float* out = (float*)d_out;
    (void)in_sizes; (void)n_in; (void)out_size;

    float *X, *XZ, *Xs, *db, *dtb, *Y;
    cudaGetSymbolAddress((void**)&X,  g_X);
    cudaGetSymbolAddress((void**)&XZ, g_XZ);
    cudaGetSymbolAddress((void**)&Xs, g_Xs);
    cudaGetSymbolAddress((void**)&db, g_db);
    cudaGetSymbolAddress((void**)&dtb, g_dt);
    cudaGetSymbolAddress((void**)&Y,  g_Y);

    __nv_bfloat16 *xnH, *xnL, *xsH, *xsL, *ygH, *ygL;
    __nv_bfloat16 *inwH, *inwL, *xpwH, *xpwL, *otwH, *otwL, *lmwH, *lmwL;
    cudaGetSymbolAddress((void**)&xnH, g_xnH);
    cudaGetSymbolAddress((void**)&xnL, g_xnL);
    cudaGetSymbolAddress((void**)&xsH, g_xsH);
    cudaGetSymbolAddress((void**)&xsL, g_xsL);
    cudaGetSymbolAddress((void**)&ygH, g_ygH);
    cudaGetSymbolAddress((void**)&ygL, g_ygL);
    cudaGetSymbolAddress((void**)&inwH, g_inwH);
    cudaGetSymbolAddress((void**)&inwL, g_inwL);
    cudaGetSymbolAddress((void**)&xpwH, g_xpwH);
    cudaGetSymbolAddress((void**)&xpwL, g_xpwL);
    cudaGetSymbolAddress((void**)&otwH, g_otwH);
    cudaGetSymbolAddress((void**)&otwL, g_otwL);
    cudaGetSymbolAddress((void**)&lmwH, g_lmwH);
    cudaGetSymbolAddress((void**)&lmwL, g_lmwL);

    cudaFuncSetAttribute(mma_tn_bf16,
                         cudaFuncAttributeMaxDynamicSharedMemorySize, SMEM_TOT);

    // ---- split all weights to (hi,lo) bf16 ----
    auto split_launch = [&](const float* src, __nv_bfloat16* h, __nv_bfloat16* l, int n) {
        int n4 = n / 4;
        split_kernel<<<(n4 + 255) / 256, 256>>>(src, h, l, n4);
    };
    split_launch(in_w,  inwH, inwL, 2 * 2 * DI * DM);
    split_launch(xp_w,  xpwH, xpwL, 2 * XDBL * DI);
    split_launch(out_w, otwH, otwL, 2 * DM * DI);
    split_launch(lm_w,  lmwH, lmwL, VOCAB * DM);

    const int EW_BLOCKS = (BL * DI + 255) / 256;

    embed_kernel<<<BL, 256>>>(tokens, wte, X);

    for (int layer = 0; layer < 2; layer++) {
        size_t inw_off = (size_t)layer * 2 * DI * DM;
        size_t xpw_off = (size_t)layer * XDBL * DI;
        size_t otw_off = (size_t)layer * DM * DI;
        const float* conv_w_l = conv_w + (size_t)layer * DI * 4;
        const float* conv_b_l = conv_b + (size_t)layer * DI;
        const float* dtp_w_l  = dtp_w  + (size_t)layer * DI * DTR;
        const float* dtp_b_l  = dtp_b  + (size_t)layer * DI;
        const float* A_log_l  = A_log  + (size_t)layer * DI * NS;
        const float* D_l      = Dvec   + (size_t)layer * DI;

        rmsnorm_split_kernel<<<BL, 256>>>(X, xnH, xnL);
        mma_tn_bf16<<<dim3(BL / 128, (2 * DI) / 128), 256, SMEM_TOT>>>(
            xnH, xnL, inwH + inw_off, inwL + inw_off, nullptr, XZ, BL, 2 * DI, DM);
        conv_silu_kernel<<<EW_BLOCKS, 256>>>(XZ, conv_w_l, conv_b_l, Xs, xsH, xsL);
        mma_tn_bf16<<<dim3(BL / 128, 1), 256, SMEM_TOT>>>(
            xsH, xsL, xpwH + xpw_off, xpwL + xpw_off, nullptr, db, BL, XDBL, DI);
        dtproj_kernel<<<EW_BLOCKS, 256>>>(db, dtp_w_l, dtp_b_l, dtb);
        scan_kernel<<<(2 * DI * NS) / 256, 256>>>(db, dtb, Xs, A_log_l, D_l, Y);
        gate_split_kernel<<<EW_BLOCKS, 256>>>(XZ, Y, ygH, ygL);
        mma_tn_bf16<<<dim3(BL / 128, DM / 128), 256, SMEM_TOT>>>(
            ygH, ygL, otwH + otw_off, otwL + otw_off, X, X, BL, DM, DI);
    }

    rmsnorm_split_kernel<<<BL, 256>>>(X, xnH, xnL);
    mma_tn_bf16<<<dim3(BL / 128, VOCAB / 128), 256, SMEM_TOT>>>(
        xnH, xnL, lmwH, lmwL, nullptr, out, BL, VOCAB, DM);
}

// round 7
// speedup vs baseline: 1.9449x; 1.0037x over previous
#include <cuda_runtime.h>
#include <cuda_bf16.h>
#include <math.h>
#include <stdint.h>

#define BL 2048      // BATCH*SEQ
#define SEQ 1024
#define DM 768
#define DI 1536
#define DTR 48
#define NS 16
#define XDBL 80      // DTR + 2*NS
#define VOCAB 50304

// ---------------- fp32 scratch ------------------------------------------------
__device__ float g_X [BL * DM];        // residual stream
__device__ float g_XZ[BL * 2 * DI];    // in_proj output (x | z)
__device__ float g_Xs[BL * DI];        // conv+silu(x) fp32 (for scan)
__device__ float g_db[BL * XDBL];      // x_proj output (dt_in | B | C)
__device__ float g_dt[BL * DI];        // softplus(dt_proj)
__device__ float g_Y [BL * DI];        // scan output

// ---------------- split-bf16 scratch -------------------------------------------
__device__ __nv_bfloat16 g_xnH[BL * DM],  g_xnL[BL * DM];    // rmsnorm out
__device__ __nv_bfloat16 g_xsH[BL * DI],  g_xsL[BL * DI];    // conv+silu out
__device__ __nv_bfloat16 g_ygH[BL * DI],  g_ygL[BL * DI];    // gated scan out
__device__ __nv_bfloat16 g_inwH[2 * 2 * DI * DM], g_inwL[2 * 2 * DI * DM];
__device__ __nv_bfloat16 g_xpwH[2 * XDBL * DI],   g_xpwL[2 * XDBL * DI];
__device__ __nv_bfloat16 g_otwH[2 * DM * DI],     g_otwL[2 * DM * DI];
__device__ __nv_bfloat16 g_lmwH[VOCAB * DM],      g_lmwL[VOCAB * DM];

// ---------------- helpers ----------------------------------------------------
__device__ __forceinline__ float siluf(float v) {
    return v / (1.f + __expf(-v));
}
__device__ __forceinline__ float softplusf(float v) {
    return v > 20.f ? v : log1pf(__expf(v));
}
__device__ __forceinline__ void split1(float v, __nv_bfloat16& h, __nv_bfloat16& l) {
    h = __float2bfloat16(v);
    l = __float2bfloat16(v - __bfloat162float(h));
}

// ---------------- fp32 -> (hi,lo) bf16 convert --------------------------------
__global__ void split_kernel(const float* __restrict__ x,
                             __nv_bfloat16* __restrict__ h,
                             __nv_bfloat16* __restrict__ l, int n4) {
    int i = blockIdx.x * blockDim.x + threadIdx.x;
    if (i >= n4) return;
    float4 v = ((const float4*)x)[i];
    __nv_bfloat16 h0, h1, h2, h3, l0, l1, l2, l3;
    split1(v.x, h0, l0); split1(v.y, h1, l1);
    split1(v.z, h2, l2); split1(v.w, h3, l3);
    ((__nv_bfloat162*)h)[i * 2 + 0] = __nv_bfloat162(h0, h1);
    ((__nv_bfloat162*)h)[i * 2 + 1] = __nv_bfloat162(h2, h3);
    ((__nv_bfloat162*)l)[i * 2 + 0] = __nv_bfloat162(l0, l1);
    ((__nv_bfloat162*)l)[i * 2 + 1] = __nv_bfloat162(l2, l3);
}

// ---------------- embedding --------------------------------------------------
__global__ void embed_kernel(const int* __restrict__ tokens,
                             const float* __restrict__ wte,
                             float* __restrict__ X) {
    int t = blockIdx.x;
    int tok = tokens[t];
    const float4* src = (const float4*)(wte + (size_t)tok * DM);
    float4* dst = (float4*)(X + (size_t)t * DM);
    for (int i = threadIdx.x; i < DM / 4; i += blockDim.x) dst[i] = src[i];
}

// ---------------- rmsnorm -> split bf16 ---------------------------------------
__global__ void rmsnorm_split_kernel(const float* __restrict__ x,
                                     __nv_bfloat16* __restrict__ oh,
                                     __nv_bfloat16* __restrict__ ol) {
    int t = blockIdx.x;
    const float* xr = x + (size_t)t * DM;
    float s = 0.f;
    for (int i = threadIdx.x; i < DM; i += blockDim.x) {
        float v = xr[i];
        s += v * v;
    }
#pragma unroll
    for (int off = 16; off; off >>= 1) s += __shfl_xor_sync(0xffffffffu, s, off);
    __shared__ float red[8];
    if ((threadIdx.x & 31) == 0) red[threadIdx.x >> 5] = s;
    __syncthreads();
    if (threadIdx.x < 32) {
        float v = (threadIdx.x < 8) ? red[threadIdx.x] : 0.f;
#pragma unroll
        for (int off = 4; off; off >>= 1) v += __shfl_xor_sync(0xffffffffu, v, off);
        if (threadIdx.x == 0) red[0] = v;
    }
    __syncthreads();
    float scale = rsqrtf(red[0] * (1.f / DM) + 1e-6f);
    for (int i = threadIdx.x; i < DM; i += blockDim.x) {
        __nv_bfloat16 h, l;
        split1(xr[i] * scale, h, l);
        oh[(size_t)t * DM + i] = h;
        ol[(size_t)t * DM + i] = l;
    }
}

// =============================================================================
// split-bf16 tensor-core TN GEMM (mma.sync m16n8k16):
//   C[M,N] = (Ah+Al)[M,K] * (Bh+Bl)[N,K]^T (+ optional fp32 addsrc)
//   ~ Ah*Bh + Ah*Bl + Al*Bh, term-outer issue order (no back-to-back RAW on acc)
// 128x128 block tile, BK=32, 3-stage cp.async, ldmatrix fragments, 8 warps.
// Grid: blockIdx.x = M (fast), blockIdx.y = N. M%128==0, K%32==0, N arbitrary.
// =============================================================================
#define BKH 32
#define SSTRH 40                       // bf16 elems per SMEM row (32 + 8 pad)
#define STG_E (128 * SSTRH)            // bf16 elems per matrix per stage
#define STG_B (STG_E * 2)              // bytes (10240)
#define SMEM_TOT (4 * 3 * STG_B)       // 4 matrices x 3 stages = 122880 B

__device__ __forceinline__ void cp_async16(unsigned dst, const void* src, int srcsize) {
    asm volatile("cp.async.cg.shared.global [%0], [%1], 16, %2;\n"
                 :: "r"(dst), "l"(src), "r"(srcsize));
}
__device__ __forceinline__ void cp_commit() {
    asm volatile("cp.async.commit_group;\n");
}
__device__ __forceinline__ void cp_wait1() {
    asm volatile("cp.async.wait_group 1;\n");
}
__device__ __forceinline__ void ldsm_x4(unsigned r[4], unsigned addr) {
    asm volatile("ldmatrix.sync.aligned.m8n8.x4.shared.b16 {%0,%1,%2,%3}, [%4];"
                 : "=r"(r[0]), "=r"(r[1]), "=r"(r[2]), "=r"(r[3]) : "r"(addr));
}

__device__ __forceinline__ void mma_bf16(float c[4], const unsigned a[4], const unsigned b[2]) {
    asm volatile(
        "mma.sync.aligned.m16n8k16.row.col.f32.bf16.bf16.f32 "
        "{%0,%1,%2,%3}, {%4,%5,%6,%7}, {%8,%9}, {%0,%1,%2,%3};\n"
        : "+f"(c[0]), "+f"(c[1]), "+f"(c[2]), "+f"(c[3])
        : "r"(a[0]), "r"(a[1]), "r"(a[2]), "r"(a[3]), "r"(b[0]), "r"(b[1]));
}

__global__ __launch_bounds__(256, 1) void mma_tn_bf16(
    const __nv_bfloat16* __restrict__ Ah, const __nv_bfloat16* __restrict__ Al,
    const __nv_bfloat16* __restrict__ Bh, const __nv_bfloat16* __restrict__ Bl,
    const float* __restrict__ addsrc, float* __restrict__ C,
    int M, int N, int K) {
    extern __shared__ __nv_bfloat16 sm[];

    const int tid  = threadIdx.x;
    const int bm   = blockIdx.x << 7;   // M fast -> B tiles reused across wave
    const int bn   = blockIdx.y << 7;
    const int warp = tid >> 5, lane = tid & 31;
    const int wm   = warp & 3;            // 0..3  (M subdiv, 32 rows)
    const int wn   = warp >> 2;           // 0..1  (N subdiv, 64 cols)
    const int g    = lane >> 2, tq = lane & 3;

    // ldmatrix lane->address mapping (element offsets within tile)
    const int a_row = (lane & 7) + 8 * ((lane >> 3) & 1);  // 0..15
    const int a_col = 8 * (lane >> 4);                     // 0 or 8
    const int b_row = (lane & 7) + 8 * (lane >> 4);        // 0..15
    const int b_col = 8 * ((lane >> 3) & 1);               // 0 or 8

    // loader: each thread does 2 rows x 1 16B-chunk per matrix per stage
    const int lrow = tid >> 2;            // 0..63
    const int lch  = tid & 3;             // 16B chunk (8 bf16)

    const unsigned sb  = (unsigned)__cvta_generic_to_shared(sm);
    const unsigned AHo = 0, ALo = 3 * STG_B, BHo = 6 * STG_B, BLo = 9 * STG_B;

    float acc[2][8][4];
#pragma unroll
    for (int i = 0; i < 2; i++)
#pragma unroll
        for (int j = 0; j < 8; j++)
#pragma unroll
            for (int q = 0; q < 4; q++) acc[i][j][q] = 0.f;

    const int KT = K / BKH;

    auto load_tile = [&](int s, int kt) {
        const int kb = kt * BKH + lch * 8;
#pragma unroll
        for (int r = 0; r < 2; r++) {
            int row = lrow + 64 * r;
            unsigned doff = (unsigned)((row * SSTRH + lch * 8) * 2 + s * STG_B);
            size_t agoff = (size_t)(bm + row) * K + kb;
            cp_async16(sb + AHo + doff, Ah + agoff, 16);
            cp_async16(sb + ALo + doff, Al + agoff, 16);
            int ok = (bn + row) < N;
            size_t bgoff = (size_t)(ok ? (bn + row) : 0) * K + kb;
            cp_async16(sb + BHo + doff, Bh + bgoff, ok ? 16 : 0);
            cp_async16(sb + BLo + doff, Bl + bgoff, ok ? 16 : 0);
        }
    };

#pragma unroll
    for (int s = 0; s < 2; s++) {
        if (s < KT) load_tile(s, s);
        cp_commit();
    }

    for (int kt = 0; kt < KT; kt++) {
        cp_wait1();
        __syncthreads();
        int nkt = kt + 2;
        if (nkt < KT) load_tile(nkt % 3, nkt);
        cp_commit();

        const unsigned stoff = (unsigned)((kt % 3) * STG_B);

#pragma unroll
        for (int ks = 0; ks < 2; ks++) {
            unsigned ah[2][4], al[2][4];
#pragma unroll
            for (int mt = 0; mt < 2; mt++) {
                unsigned off = (unsigned)(((wm * 32 + mt * 16 + a_row) * SSTRH
                                           + ks * 16 + a_col) * 2);
                ldsm_x4(ah[mt], sb + AHo + stoff + off);
                ldsm_x4(al[mt], sb + ALo + stoff + off);
            }
            unsigned bh[8][2], bl[8][2];
#pragma unroll
            for (int grp = 0; grp < 4; grp++) {
                unsigned off = (unsigned)(((wn * 64 + grp * 16 + b_row) * SSTRH
                                           + ks * 16 + b_col) * 2);
                unsigned t[4];
                ldsm_x4(t, sb + BHo + stoff + off);
                bh[grp * 2][0] = t[0]; bh[grp * 2][1] = t[1];
                bh[grp * 2 + 1][0] = t[2]; bh[grp * 2 + 1][1] = t[3];
                ldsm_x4(t, sb + BLo + stoff + off);
                bl[grp * 2][0] = t[0]; bl[grp * 2][1] = t[1];
                bl[grp * 2 + 1][0] = t[2]; bl[grp * 2 + 1][1] = t[3];
            }
            // term-outer: all 16 hh, then 16 hl, then 16 lh -> no
            // back-to-back RAW on any accumulator (reuse distance = 16 MMAs)
#pragma unroll
            for (int mt = 0; mt < 2; mt++)
#pragma unroll
                for (int nt = 0; nt < 8; nt++)
                    mma_bf16(acc[mt][nt], ah[mt], bh[nt]);
#pragma unroll
            for (int mt = 0; mt < 2; mt++)
#pragma unroll
                for (int nt = 0; nt < 8; nt++)
                    mma_bf16(acc[mt][nt], ah[mt], bl[nt]);
#pragma unroll
            for (int mt = 0; mt < 2; mt++)
#pragma unroll
                for (int nt = 0; nt < 8; nt++)
                    mma_bf16(acc[mt][nt], al[mt], bh[nt]);
        }
        __syncthreads();
    }

    // ---- epilogue ----
#pragma unroll
    for (int mt = 0; mt < 2; mt++) {
        int row0 = bm + wm * 32 + mt * 16 + g;
#pragma unroll
        for (int nt = 0; nt < 8; nt++) {
            int col = bn + wn * 64 + nt * 8 + tq * 2;
            if (col + 1 < N) {
                size_t o0 = (size_t)row0 * N + col;
                size_t o1 = (size_t)(row0 + 8) * N + col;
                float2 v0 = make_float2(acc[mt][nt][0], acc[mt][nt][1]);
                float2 v1 = make_float2(acc[mt][nt][2], acc[mt][nt][3]);
                if (addsrc) {
                    const float2 r0 = *(const float2*)(addsrc + o0);
                    const float2 r1 = *(const float2*)(addsrc + o1);
                    v0.x += r0.x; v0.y += r0.y;
                    v1.x += r1.x; v1.y += r1.y;
                }
                *(float2*)(C + o0) = v0;
                *(float2*)(C + o1) = v1;
            } else if (col < N) {
                size_t o0 = (size_t)row0 * N + col;
                size_t o1 = (size_t)(row0 + 8) * N + col;
                float v0 = acc[mt][nt][0], v1 = acc[mt][nt][2];
                if (addsrc) { v0 += addsrc[o0]; v1 += addsrc[o1]; }
                C[o0] = v0;
                C[o1] = v1;
            }
        }
    }
}

// ---------------- depthwise causal conv (width 4) + silu, split out ----------
__global__ void conv_silu_kernel(const float* __restrict__ XZ,
                                 const float* __restrict__ cw,
                                 const float* __restrict__ cb,
                                 float* __restrict__ out,
                                 __nv_bfloat16* __restrict__ oh,
                                 __nv_bfloat16* __restrict__ ol) {
    int idx = blockIdx.x * blockDim.x + threadIdx.x;
    if (idx >= BL * DI) return;
    int t = idx / DI, d = idx - t * DI;
    int l = t & (SEQ - 1);
    const float* w = cw + d * 4;
    float s = cb[d];
    s = fmaf(w[3], XZ[(size_t)t * (2 * DI) + d], s);
    if (l >= 1) s = fmaf(w[2], XZ[(size_t)(t - 1) * (2 * DI) + d], s);
    if (l >= 2) s = fmaf(w[1], XZ[(size_t)(t - 2) * (2 * DI) + d], s);
    if (l >= 3) s = fmaf(w[0], XZ[(size_t)(t - 3) * (2 * DI) + d], s);
    float v = siluf(s);
    out[idx] = v;
    __nv_bfloat16 h, lo;
    split1(v, h, lo);
    oh[idx] = h;
    ol[idx] = lo;
}

// ---------------- dt_proj (K=48) + bias + softplus ----------------------------
__global__ void dtproj_kernel(const float* __restrict__ dbl,
                              const float* __restrict__ W,
                              const float* __restrict__ bias,
                              float* __restrict__ out) {
    int idx = blockIdx.x * blockDim.x + threadIdx.x;
    if (idx >= BL * DI) return;
    int t = idx / DI, d = idx - t * DI;
    const float4* a = (const float4*)(dbl + (size_t)t * XDBL);
    const float4* w = (const float4*)(W + (size_t)d * DTR);
    float s = bias[d];
#pragma unroll
    for (int r = 0; r < DTR / 4; r++) {
        float4 av = a[r], wv = w[r];
        s = fmaf(av.x, wv.x, s);
        s = fmaf(av.y, wv.y, s);
        s = fmaf(av.z, wv.z, s);
        s = fmaf(av.w, wv.w, s);
    }
    out[idx] = softplusf(s);
}

// ---------------- selective scan ----------------------------------------------
__global__ void scan_kernel(const float* __restrict__ dbl,
                            const float* __restrict__ dt,
                            const float* __restrict__ xs,
                            const float* __restrict__ A_log,
                            const float* __restrict__ Dvec,
                            float* __restrict__ y) {
    int gid = blockIdx.x * blockDim.x + threadIdx.x;
    int lane = threadIdx.x & 15;
    int ch = gid >> 4;
    if (ch >= 2 * DI) return;
    int b = ch / DI, d = ch - b * DI;
    float A = -expf(A_log[d * NS + lane]);
    float Dd = Dvec[d];
    float h = 0.f;
    const int tbase = b * SEQ;
    for (int l = 0; l < SEQ; l++) {
        int t = tbase + l;
        float dtv = dt[(size_t)t * DI + d];
        float xv = xs[(size_t)t * DI + d];
        float Bv = dbl[(size_t)t * XDBL + DTR + lane];
        float Cv = dbl[(size_t)t * XDBL + DTR + NS + lane];
        h = fmaf(__expf(dtv * A), h, dtv * Bv * xv);
        float p = h * Cv;
        p += __shfl_xor_sync(0xffffffffu, p, 8, 16);
        p += __shfl_xor_sync(0xffffffffu, p, 4, 16);
        p += __shfl_xor_sync(0xffffffffu, p, 2, 16);
        p += __shfl_xor_sync(0xffffffffu, p, 1, 16);
        if (lane == 0) y[(size_t)t * DI + d] = fmaf(Dd, xv, p);
    }
}

// ---------------- gate: yg = y * silu(z), split out ----------------------------
__global__ void gate_split_kernel(const float* __restrict__ XZ,
                                  const float* __restrict__ Y,
                                  __nv_bfloat16* __restrict__ oh,
                                  __nv_bfloat16* __restrict__ ol) {
    int idx = blockIdx.x * blockDim.x + threadIdx.x;
    if (idx >= BL * DI) return;
    int t = idx / DI, d = idx - t * DI;
    float z = XZ[(size_t)t * (2 * DI) + DI + d];
    float v = Y[idx] * siluf(z);
    __nv_bfloat16 h, lo;
    split1(v, h, lo);
    oh[idx] = h;
    ol[idx] = lo;
}

// ---------------- launch -------------------------------------------------------
extern "C" void kernel_launch(void* const* d_in, const int* in_sizes, int n_in,
                              void* d_out, int out_size) {
    const int*   tokens = (const int*)  d_in[0];
    const float* wte    = (const float*)d_in[1];
    const float* in_w   = (const float*)d_in[2];
    const float* conv_w = (const float*)d_in[3];
    const float* conv_b = (const float*)d_in[4];
    const float* xp_w   = (const float*)d_in[5];
    const float* dtp_w  = (const float*)d_in[6];
    const float* dtp_b  = (const float*)d_in[7];
    const float* out_w  = (const float*)d_in[8];
    const float* A_log  = (const float*)d_in[9];
    const float* Dvec   = (const float*)d_in[10];
    const float* lm_w   = (const float*)d_in[11];
    float* out = (float*)d_out;
    (void)in_sizes; (void)n_in; (void)out_size;

    float *X, *XZ, *Xs, *db, *dtb, *Y;
    cudaGetSymbolAddress((void**)&X,  g_X);
    cudaGetSymbolAddress((void**)&XZ, g_XZ);
    cudaGetSymbolAddress((void**)&Xs, g_Xs);
    cudaGetSymbolAddress((void**)&db, g_db);
    cudaGetSymbolAddress((void**)&dtb, g_dt);
    cudaGetSymbolAddress((void**)&Y,  g_Y);

    __nv_bfloat16 *xnH, *xnL, *xsH, *xsL, *ygH, *ygL;
    __nv_bfloat16 *inwH, *inwL, *xpwH, *xpwL, *otwH, *otwL, *lmwH, *lmwL;
    cudaGetSymbolAddress((void**)&xnH, g_xnH);
    cudaGetSymbolAddress((void**)&xnL, g_xnL);
    cudaGetSymbolAddress((void**)&xsH, g_xsH);
    cudaGetSymbolAddress((void**)&xsL, g_xsL);
    cudaGetSymbolAddress((void**)&ygH, g_ygH);
    cudaGetSymbolAddress((void**)&ygL, g_ygL);
    cudaGetSymbolAddress((void**)&inwH, g_inwH);
    cudaGetSymbolAddress((void**)&inwL, g_inwL);
    cudaGetSymbolAddress((void**)&xpwH, g_xpwH);
    cudaGetSymbolAddress((void**)&xpwL, g_xpwL);
    cudaGetSymbolAddress((void**)&otwH, g_otwH);
    cudaGetSymbolAddress((void**)&otwL, g_otwL);
    cudaGetSymbolAddress((void**)&lmwH, g_lmwH);
    cudaGetSymbolAddress((void**)&lmwL, g_lmwL);

    cudaFuncSetAttribute(mma_tn_bf16,
                         cudaFuncAttributeMaxDynamicSharedMemorySize, SMEM_TOT);

    auto split_launch = [&](const float* src, __nv_bfloat16* h, __nv_bfloat16* l, int n) {
        int n4 = n / 4;
        split_kernel<<<(n4 + 255) / 256, 256>>>(src, h, l, n4);
    };

    const int EW_BLOCKS = (BL * DI + 255) / 256;

    // Launch order arranged so the in_proj GEMM (layer 0) is launch index 5:
    // 0:embed 1:split_inw 2:rmsnorm 3:split_xpw 4:split_otw 5:GEMM ...
    // (ncu capture is -s 5 -c 1 -> profiles the GEMM)
    embed_kernel<<<BL, 256>>>(tokens, wte, X);                       // 0
    split_launch(in_w,  inwH, inwL, 2 * 2 * DI * DM);                // 1

    __nv_bfloat16 *xnH_ = xnH, *xnL_ = xnL;
    rmsnorm_split_kernel<<<BL, 256>>>(X, xnH_, xnL_);                // 2
    split_launch(xp_w,  xpwH, xpwL, 2 * XDBL * DI);                  // 3
    split_launch(out_w, otwH, otwL, 2 * DM * DI);                    // 4

    for (int layer = 0; layer < 2; layer++) {
        size_t inw_off = (size_t)layer * 2 * DI * DM;
        size_t xpw_off = (size_t)layer * XDBL * DI;
        size_t otw_off = (size_t)layer * DM * DI;
        const float* conv_w_l = conv_w + (size_t)layer * DI * 4;
        const float* conv_b_l = conv_b + (size_t)layer * DI;
        const float* dtp_w_l  = dtp_w  + (size_t)layer * DI * DTR;
        const float* dtp_b_l  = dtp_b  + (size_t)layer * DI;
        const float* A_log_l  = A_log  + (size_t)layer * DI * NS;
        const float* D_l      = Dvec   + (size_t)layer * DI;

        if (layer > 0)
            rmsnorm_split_kernel<<<BL, 256>>>(X, xnH, xnL);
        mma_tn_bf16<<<dim3(BL / 128, (2 * DI) / 128), 256, SMEM_TOT>>>(   // 5 for layer 0
            xnH, xnL, inwH + inw_off, inwL + inw_off, nullptr, XZ, BL, 2 * DI, DM);
        conv_silu_kernel<<<EW_BLOCKS, 256>>>(XZ, conv_w_l, conv_b_l, Xs, xsH, xsL);
        mma_tn_bf16<<<dim3(BL / 128, 1), 256, SMEM_TOT>>>(
            xsH, xsL, xpwH + xpw_off, xpwL + xpw_off, nullptr, db, BL, XDBL, DI);
        dtproj_kernel<<<EW_BLOCKS, 256>>>(db, dtp_w_l, dtp_b_l, dtb);
        scan_kernel<<<(2 * DI * NS) / 256, 256>>>(db, dtb, Xs, A_log_l, D_l, Y);
        gate_split_kernel<<<EW_BLOCKS, 256>>>(XZ, Y, ygH, ygL);
        mma_tn_bf16<<<dim3(BL / 128, DM / 128), 256, SMEM_TOT>>>(
            ygH, ygL, otwH + otw_off, otwL + otw_off, X, X, BL, DM, DI);
    }

    split_launch(lm_w, lmwH, lmwL, VOCAB * DM);
    rmsnorm_split_kernel<<<BL, 256>>>(X, xnH, xnL);
    mma_tn_bf16<<<dim3(BL / 128, VOCAB / 128), 256, SMEM_TOT>>>(
        xnH, xnL, lmwH, lmwL, nullptr, out, BL, VOCAB, DM);
}

// round 8
// speedup vs baseline: 2.0900x; 1.0746x over previous
#include <cuda_runtime.h>
#include <cuda_bf16.h>
#include <math.h>
#include <stdint.h>

#define BL 2048      // BATCH*SEQ
#define SEQ 1024
#define DM 768
#define DI 1536
#define DTR 48
#define NS 16
#define XDBL 80      // DTR + 2*NS
#define VOCAB 50304

// ---------------- fp32 scratch ------------------------------------------------
__device__ float g_X [BL * DM];        // residual stream
__device__ float g_XZ[BL * 2 * DI];    // in_proj output (x | z)
__device__ float g_Xs[BL * DI];        // conv+silu(x) fp32 (for scan)
__device__ float g_db[BL * XDBL];      // x_proj output (dt_in | B | C)
__device__ float g_dt[BL * DI];        // softplus(dt_proj)
__device__ float g_Y [BL * DI];        // scan output

// ---------------- split-bf16 scratch -------------------------------------------
__device__ __nv_bfloat16 g_xnH[BL * DM],  g_xnL[BL * DM];    // rmsnorm out
__device__ __nv_bfloat16 g_xsH[BL * DI],  g_xsL[BL * DI];    // conv+silu out
__device__ __nv_bfloat16 g_ygH[BL * DI],  g_ygL[BL * DI];    // gated scan out
__device__ __nv_bfloat16 g_inwH[2 * 2 * DI * DM], g_inwL[2 * 2 * DI * DM];
__device__ __nv_bfloat16 g_xpwH[2 * XDBL * DI],   g_xpwL[2 * XDBL * DI];
__device__ __nv_bfloat16 g_otwH[2 * DM * DI],     g_otwL[2 * DM * DI];
__device__ __nv_bfloat16 g_lmwH[VOCAB * DM],      g_lmwL[VOCAB * DM];

// ---------------- helpers ----------------------------------------------------
__device__ __forceinline__ float siluf(float v) {
    return v / (1.f + __expf(-v));
}
__device__ __forceinline__ float softplusf(float v) {
    return v > 20.f ? v : log1pf(__expf(v));
}
__device__ __forceinline__ void split1(float v, __nv_bfloat16& h, __nv_bfloat16& l) {
    h = __float2bfloat16(v);
    l = __float2bfloat16(v - __bfloat162float(h));
}

// ---------------- fp32 -> (hi,lo) bf16 convert --------------------------------
__global__ void split_kernel(const float* __restrict__ x,
                             __nv_bfloat16* __restrict__ h,
                             __nv_bfloat16* __restrict__ l, int n4) {
    int i = blockIdx.x * blockDim.x + threadIdx.x;
    if (i >= n4) return;
    float4 v = ((const float4*)x)[i];
    __nv_bfloat16 h0, h1, h2, h3, l0, l1, l2, l3;
    split1(v.x, h0, l0); split1(v.y, h1, l1);
    split1(v.z, h2, l2); split1(v.w, h3, l3);
    ((__nv_bfloat162*)h)[i * 2 + 0] = __nv_bfloat162(h0, h1);
    ((__nv_bfloat162*)h)[i * 2 + 1] = __nv_bfloat162(h2, h3);
    ((__nv_bfloat162*)l)[i * 2 + 0] = __nv_bfloat162(l0, l1);
    ((__nv_bfloat162*)l)[i * 2 + 1] = __nv_bfloat162(l2, l3);
}

// ---------------- embedding --------------------------------------------------
__global__ void embed_kernel(const int* __restrict__ tokens,
                             const float* __restrict__ wte,
                             float* __restrict__ X) {
    int t = blockIdx.x;
    int tok = tokens[t];
    const float4* src = (const float4*)(wte + (size_t)tok * DM);
    float4* dst = (float4*)(X + (size_t)t * DM);
    for (int i = threadIdx.x; i < DM / 4; i += blockDim.x) dst[i] = src[i];
}

// ---------------- rmsnorm -> split bf16 ---------------------------------------
__global__ void rmsnorm_split_kernel(const float* __restrict__ x,
                                     __nv_bfloat16* __restrict__ oh,
                                     __nv_bfloat16* __restrict__ ol) {
    int t = blockIdx.x;
    const float* xr = x + (size_t)t * DM;
    float s = 0.f;
    for (int i = threadIdx.x; i < DM; i += blockDim.x) {
        float v = xr[i];
        s += v * v;
    }
#pragma unroll
    for (int off = 16; off; off >>= 1) s += __shfl_xor_sync(0xffffffffu, s, off);
    __shared__ float red[8];
    if ((threadIdx.x & 31) == 0) red[threadIdx.x >> 5] = s;
    __syncthreads();
    if (threadIdx.x < 32) {
        float v = (threadIdx.x < 8) ? red[threadIdx.x] : 0.f;
#pragma unroll
        for (int off = 4; off; off >>= 1) v += __shfl_xor_sync(0xffffffffu, v, off);
        if (threadIdx.x == 0) red[0] = v;
    }
    __syncthreads();
    float scale = rsqrtf(red[0] * (1.f / DM) + 1e-6f);
    for (int i = threadIdx.x; i < DM; i += blockDim.x) {
        __nv_bfloat16 h, l;
        split1(xr[i] * scale, h, l);
        oh[(size_t)t * DM + i] = h;
        ol[(size_t)t * DM + i] = l;
    }
}

// =============================================================================
// split-bf16 tensor-core TN GEMM (mma.sync m16n8k16):
//   C[M,N] = (Ah+Al)[M,K] * (Bh+Bl)[N,K]^T (+ optional fp32 addsrc)
//   ~ Ah*Bh + Ah*Bl + Al*Bh
// 128x128 block tile, BK=32, 2-stage cp.async double buffer, 8 warps,
// 2 CTAs/SM (smem 80KB). ldmatrix fragments.
// Grid: blockIdx.x = M (fast), blockIdx.y = N. M%128==0, K%32==0, N arbitrary.
// =============================================================================
#define BKH 32
#define SSTRH 40                       // bf16 elems per SMEM row (32 + 8 pad)
#define STG_E (128 * SSTRH)            // bf16 elems per matrix per stage
#define STG_B (STG_E * 2)              // bytes (10240)
#define NSTG 2
#define SMEM_TOT (4 * NSTG * STG_B)    // 81920 B -> 2 CTAs/SM

__device__ __forceinline__ void cp_async16(unsigned dst, const void* src, int srcsize) {
    asm volatile("cp.async.cg.shared.global [%0], [%1], 16, %2;\n"
                 :: "r"(dst), "l"(src), "r"(srcsize));
}
__device__ __forceinline__ void cp_commit() {
    asm volatile("cp.async.commit_group;\n");
}
__device__ __forceinline__ void cp_wait1() {
    asm volatile("cp.async.wait_group 1;\n");
}
__device__ __forceinline__ void ldsm_x4(unsigned r[4], unsigned addr) {
    asm volatile("ldmatrix.sync.aligned.m8n8.x4.shared.b16 {%0,%1,%2,%3}, [%4];"
                 : "=r"(r[0]), "=r"(r[1]), "=r"(r[2]), "=r"(r[3]) : "r"(addr));
}

__device__ __forceinline__ void mma_bf16(float c[4], const unsigned a[4], const unsigned b[2]) {
    asm volatile(
        "mma.sync.aligned.m16n8k16.row.col.f32.bf16.bf16.f32 "
        "{%0,%1,%2,%3}, {%4,%5,%6,%7}, {%8,%9}, {%0,%1,%2,%3};\n"
        : "+f"(c[0]), "+f"(c[1]), "+f"(c[2]), "+f"(c[3])
        : "r"(a[0]), "r"(a[1]), "r"(a[2]), "r"(a[3]), "r"(b[0]), "r"(b[1]));
}

__global__ __launch_bounds__(256, 2) void mma_tn_bf16(
    const __nv_bfloat16* __restrict__ Ah, const __nv_bfloat16* __restrict__ Al,
    const __nv_bfloat16* __restrict__ Bh, const __nv_bfloat16* __restrict__ Bl,
    const float* __restrict__ addsrc, float* __restrict__ C,
    int M, int N, int K) {
    extern __shared__ __nv_bfloat16 sm[];

    const int tid  = threadIdx.x;
    const int bm   = blockIdx.x << 7;   // M fast -> B tiles reused across wave
    const int bn   = blockIdx.y << 7;
    const int warp = tid >> 5, lane = tid & 31;
    const int wm   = warp & 3;            // 0..3  (M subdiv, 32 rows)
    const int wn   = warp >> 2;           // 0..1  (N subdiv, 64 cols)
    const int g    = lane >> 2, tq = lane & 3;

    // ldmatrix lane->address mapping (element offsets within tile)
    const int a_row = (lane & 7) + 8 * ((lane >> 3) & 1);  // 0..15
    const int a_col = 8 * (lane >> 4);                     // 0 or 8
    const int b_row = (lane & 7) + 8 * (lane >> 4);        // 0..15
    const int b_col = 8 * ((lane >> 3) & 1);               // 0 or 8

    // loader: each thread does 2 rows x 1 16B-chunk per matrix per stage
    const int lrow = tid >> 2;            // 0..63
    const int lch  = tid & 3;             // 16B chunk (8 bf16)

    const unsigned sb  = (unsigned)__cvta_generic_to_shared(sm);
    const unsigned AHo = 0, ALo = NSTG * STG_B, BHo = 2 * NSTG * STG_B,
                   BLo = 3 * NSTG * STG_B;

    float acc[2][8][4];
#pragma unroll
    for (int i = 0; i < 2; i++)
#pragma unroll
        for (int j = 0; j < 8; j++)
#pragma unroll
            for (int q = 0; q < 4; q++) acc[i][j][q] = 0.f;

    const int KT = K / BKH;

    auto load_tile = [&](int s, int kt) {
        const int kb = kt * BKH + lch * 8;
#pragma unroll
        for (int r = 0; r < 2; r++) {
            int row = lrow + 64 * r;
            unsigned doff = (unsigned)((row * SSTRH + lch * 8) * 2 + s * STG_B);
            size_t agoff = (size_t)(bm + row) * K + kb;
            cp_async16(sb + AHo + doff, Ah + agoff, 16);
            cp_async16(sb + ALo + doff, Al + agoff, 16);
            int ok = (bn + row) < N;
            size_t bgoff = (size_t)(ok ? (bn + row) : 0) * K + kb;
            cp_async16(sb + BHo + doff, Bh + bgoff, ok ? 16 : 0);
            cp_async16(sb + BLo + doff, Bl + bgoff, ok ? 16 : 0);
        }
    };

    load_tile(0, 0);
    cp_commit();

    for (int kt = 0; kt < KT; kt++) {
        // prefetch next k-tile into the other stage
        if (kt + 1 < KT) load_tile((kt + 1) & 1, kt + 1);
        cp_commit();
        cp_wait1();                      // load kt complete; kt+1 in flight
        __syncthreads();

        const unsigned stoff = (unsigned)((kt & 1) * STG_B);

#pragma unroll
        for (int ks = 0; ks < 2; ks++) {
            unsigned ah[2][4], al[2][4];
#pragma unroll
            for (int mt = 0; mt < 2; mt++) {
                unsigned off = (unsigned)(((wm * 32 + mt * 16 + a_row) * SSTRH
                                           + ks * 16 + a_col) * 2);
                ldsm_x4(ah[mt], sb + AHo + stoff + off);
                ldsm_x4(al[mt], sb + ALo + stoff + off);
            }
            unsigned bh[8][2], bl[8][2];
#pragma unroll
            for (int grp = 0; grp < 4; grp++) {
                unsigned off = (unsigned)(((wn * 64 + grp * 16 + b_row) * SSTRH
                                           + ks * 16 + b_col) * 2);
                unsigned t[4];
                ldsm_x4(t, sb + BHo + stoff + off);
                bh[grp * 2][0] = t[0]; bh[grp * 2][1] = t[1];
                bh[grp * 2 + 1][0] = t[2]; bh[grp * 2 + 1][1] = t[3];
                ldsm_x4(t, sb + BLo + stoff + off);
                bl[grp * 2][0] = t[0]; bl[grp * 2][1] = t[1];
                bl[grp * 2 + 1][0] = t[2]; bl[grp * 2 + 1][1] = t[3];
            }
#pragma unroll
            for (int mt = 0; mt < 2; mt++)
#pragma unroll
                for (int nt = 0; nt < 8; nt++)
                    mma_bf16(acc[mt][nt], ah[mt], bh[nt]);
#pragma unroll
            for (int mt = 0; mt < 2; mt++)
#pragma unroll
                for (int nt = 0; nt < 8; nt++)
                    mma_bf16(acc[mt][nt], ah[mt], bl[nt]);
#pragma unroll
            for (int mt = 0; mt < 2; mt++)
#pragma unroll
                for (int nt = 0; nt < 8; nt++)
                    mma_bf16(acc[mt][nt], al[mt], bh[nt]);
        }
        __syncthreads();
    }

    // ---- epilogue ----
#pragma unroll
    for (int mt = 0; mt < 2; mt++) {
        int row0 = bm + wm * 32 + mt * 16 + g;
#pragma unroll
        for (int nt = 0; nt < 8; nt++) {
            int col = bn + wn * 64 + nt * 8 + tq * 2;
            if (col + 1 < N) {
                size_t o0 = (size_t)row0 * N + col;
                size_t o1 = (size_t)(row0 + 8) * N + col;
                float2 v0 = make_float2(acc[mt][nt][0], acc[mt][nt][1]);
                float2 v1 = make_float2(acc[mt][nt][2], acc[mt][nt][3]);
                if (addsrc) {
                    const float2 r0 = *(const float2*)(addsrc + o0);
                    const float2 r1 = *(const float2*)(addsrc + o1);
                    v0.x += r0.x; v0.y += r0.y;
                    v1.x += r1.x; v1.y += r1.y;
                }
                *(float2*)(C + o0) = v0;
                *(float2*)(C + o1) = v1;
            } else if (col < N) {
                size_t o0 = (size_t)row0 * N + col;
                size_t o1 = (size_t)(row0 + 8) * N + col;
                float v0 = acc[mt][nt][0], v1 = acc[mt][nt][2];
                if (addsrc) { v0 += addsrc[o0]; v1 += addsrc[o1]; }
                C[o0] = v0;
                C[o1] = v1;
            }
        }
    }
}

// ---------------- depthwise causal conv (width 4) + silu, split out ----------
__global__ void conv_silu_kernel(const float* __restrict__ XZ,
                                 const float* __restrict__ cw,
                                 const float* __restrict__ cb,
                                 float* __restrict__ out,
                                 __nv_bfloat16* __restrict__ oh,
                                 __nv_bfloat16* __restrict__ ol) {
    int idx = blockIdx.x * blockDim.x + threadIdx.x;
    if (idx >= BL * DI) return;
    int t = idx / DI, d = idx - t * DI;
    int l = t & (SEQ - 1);
    const float* w = cw + d * 4;
    float s = cb[d];
    s = fmaf(w[3], XZ[(size_t)t * (2 * DI) + d], s);
    if (l >= 1) s = fmaf(w[2], XZ[(size_t)(t - 1) * (2 * DI) + d], s);
    if (l >= 2) s = fmaf(w[1], XZ[(size_t)(t - 2) * (2 * DI) + d], s);
    if (l >= 3) s = fmaf(w[0], XZ[(size_t)(t - 3) * (2 * DI) + d], s);
    float v = siluf(s);
    out[idx] = v;
    __nv_bfloat16 h, lo;
    split1(v, h, lo);
    oh[idx] = h;
    ol[idx] = lo;
}

// ---------------- dt_proj (K=48) + bias + softplus ----------------------------
__global__ void dtproj_kernel(const float* __restrict__ dbl,
                              const float* __restrict__ W,
                              const float* __restrict__ bias,
                              float* __restrict__ out) {
    int idx = blockIdx.x * blockDim.x + threadIdx.x;
    if (idx >= BL * DI) return;
    int t = idx / DI, d = idx - t * DI;
    const float4* a = (const float4*)(dbl + (size_t)t * XDBL);
    const float4* w = (const float4*)(W + (size_t)d * DTR);
    float s = bias[d];
#pragma unroll
    for (int r = 0; r < DTR / 4; r++) {
        float4 av = a[r], wv = w[r];
        s = fmaf(av.x, wv.x, s);
        s = fmaf(av.y, wv.y, s);
        s = fmaf(av.z, wv.z, s);
        s = fmaf(av.w, wv.w, s);
    }
    out[idx] = softplusf(s);
}

// ---------------- selective scan ----------------------------------------------
__global__ void scan_kernel(const float* __restrict__ dbl,
                            const float* __restrict__ dt,
                            const float* __restrict__ xs,
                            const float* __restrict__ A_log,
                            const float* __restrict__ Dvec,
                            float* __restrict__ y) {
    int gid = blockIdx.x * blockDim.x + threadIdx.x;
    int lane = threadIdx.x & 15;
    int ch = gid >> 4;
    if (ch >= 2 * DI) return;
    int b = ch / DI, d = ch - b * DI;
    float A = -expf(A_log[d * NS + lane]);
    float Dd = Dvec[d];
    float h = 0.f;
    const int tbase = b * SEQ;
    for (int l = 0; l < SEQ; l++) {
        int t = tbase + l;
        float dtv = dt[(size_t)t * DI + d];
        float xv = xs[(size_t)t * DI + d];
        float Bv = dbl[(size_t)t * XDBL + DTR + lane];
        float Cv = dbl[(size_t)t * XDBL + DTR + NS + lane];
        h = fmaf(__expf(dtv * A), h, dtv * Bv * xv);
        float p = h * Cv;
        p += __shfl_xor_sync(0xffffffffu, p, 8, 16);
        p += __shfl_xor_sync(0xffffffffu, p, 4, 16);
        p += __shfl_xor_sync(0xffffffffu, p, 2, 16);
        p += __shfl_xor_sync(0xffffffffu, p, 1, 16);
        if (lane == 0) y[(size_t)t * DI + d] = fmaf(Dd, xv, p);
    }
}

// ---------------- gate: yg = y * silu(z), split out ----------------------------
__global__ void gate_split_kernel(const float* __restrict__ XZ,
                                  const float* __restrict__ Y,
                                  __nv_bfloat16* __restrict__ oh,
                                  __nv_bfloat16* __restrict__ ol) {
    int idx = blockIdx.x * blockDim.x + threadIdx.x;
    if (idx >= BL * DI) return;
    int t = idx / DI, d = idx - t * DI;
    float z = XZ[(size_t)t * (2 * DI) + DI + d];
    float v = Y[idx] * siluf(z);
    __nv_bfloat16 h, lo;
    split1(v, h, lo);
    oh[idx] = h;
    ol[idx] = lo;
}

// ---------------- launch -------------------------------------------------------
extern "C" void kernel_launch(void* const* d_in, const int* in_sizes, int n_in,
                              void* d_out, int out_size) {
    const int*   tokens = (const int*)  d_in[0];
    const float* wte    = (const float*)d_in[1];
    const float* in_w   = (const float*)d_in[2];
    const float* conv_w = (const float*)d_in[3];
    const float* conv_b = (const float*)d_in[4];
    const float* xp_w   = (const float*)d_in[5];
    const float* dtp_w  = (const float*)d_in[6];
    const float* dtp_b  = (const float*)d_in[7];
    const float* out_w  = (const float*)d_in[8];
    const float* A_log  = (const float*)d_in[9];
    const float* Dvec   = (const float*)d_in[10];
    const float* lm_w   = (const float*)d_in[11];
    float* out = (float*)d_out;
    (void)in_sizes; (void)n_in; (void)out_size;

    float *X, *XZ, *Xs, *db, *dtb, *Y;
    cudaGetSymbolAddress((void**)&X,  g_X);
    cudaGetSymbolAddress((void**)&XZ, g_XZ);
    cudaGetSymbolAddress((void**)&Xs, g_Xs);
    cudaGetSymbolAddress((void**)&db, g_db);
    cudaGetSymbolAddress((void**)&dtb, g_dt);
    cudaGetSymbolAddress((void**)&Y,  g_Y);

    __nv_bfloat16 *xnH, *xnL, *xsH, *xsL, *ygH, *ygL;
    __nv_bfloat16 *inwH, *inwL, *xpwH, *xpwL, *otwH, *otwL, *lmwH, *lmwL;
    cudaGetSymbolAddress((void**)&xnH, g_xnH);
    cudaGetSymbolAddress((void**)&xnL, g_xnL);
    cudaGetSymbolAddress((void**)&xsH, g_xsH);
    cudaGetSymbolAddress((void**)&xsL, g_xsL);
    cudaGetSymbolAddress((void**)&ygH, g_ygH);
    cudaGetSymbolAddress((void**)&ygL, g_ygL);
    cudaGetSymbolAddress((void**)&inwH, g_inwH);
    cudaGetSymbolAddress((void**)&inwL, g_inwL);
    cudaGetSymbolAddress((void**)&xpwH, g_xpwH);
    cudaGetSymbolAddress((void**)&xpwL, g_xpwL);
    cudaGetSymbolAddress((void**)&otwH, g_otwH);
    cudaGetSymbolAddress((void**)&otwL, g_otwL);
    cudaGetSymbolAddress((void**)&lmwH, g_lmwH);
    cudaGetSymbolAddress((void**)&lmwL, g_lmwL);

    cudaFuncSetAttribute(mma_tn_bf16,
                         cudaFuncAttributeMaxDynamicSharedMemorySize, SMEM_TOT);

    auto split_launch = [&](const float* src, __nv_bfloat16* h, __nv_bfloat16* l, int n) {
        int n4 = n / 4;
        split_kernel<<<(n4 + 255) / 256, 256>>>(src, h, l, n4);
    };

    const int EW_BLOCKS = (BL * DI + 255) / 256;

    // Launch order: embed(0), split_inw(1), rmsnorm(2), GEMM(3) — the ncu
    // -s 5 capture (2 harness launches precede ours) should hit the GEMM.
    embed_kernel<<<BL, 256>>>(tokens, wte, X);                       // 0
    split_launch(in_w,  inwH, inwL, 2 * 2 * DI * DM);                // 1
    rmsnorm_split_kernel<<<BL, 256>>>(X, xnH, xnL);                  // 2

    for (int layer = 0; layer < 2; layer++) {
        size_t inw_off = (size_t)layer * 2 * DI * DM;
        size_t xpw_off = (size_t)layer * XDBL * DI;
        size_t otw_off = (size_t)layer * DM * DI;
        const float* conv_w_l = conv_w + (size_t)layer * DI * 4;
        const float* conv_b_l = conv_b + (size_t)layer * DI;
        const float* dtp_w_l  = dtp_w  + (size_t)layer * DI * DTR;
        const float* dtp_b_l  = dtp_b  + (size_t)layer * DI;
        const float* A_log_l  = A_log  + (size_t)layer * DI * NS;
        const float* D_l      = Dvec   + (size_t)layer * DI;

        if (layer > 0)
            rmsnorm_split_kernel<<<BL, 256>>>(X, xnH, xnL);
        mma_tn_bf16<<<dim3(BL / 128, (2 * DI) / 128), 256, SMEM_TOT>>>(  // 3 for layer 0
            xnH, xnL, inwH + inw_off, inwL + inw_off, nullptr, XZ, BL, 2 * DI, DM);
        if (layer == 0) {
            split_launch(xp_w,  xpwH, xpwL, 2 * XDBL * DI);
            split_launch(out_w, otwH, otwL, 2 * DM * DI);
        }
        conv_silu_kernel<<<EW_BLOCKS, 256>>>(XZ, conv_w_l, conv_b_l, Xs, xsH, xsL);
        mma_tn_bf16<<<dim3(BL / 128, 1), 256, SMEM_TOT>>>(
            xsH, xsL, xpwH + xpw_off, xpwL + xpw_off, nullptr, db, BL, XDBL, DI);
        dtproj_kernel<<<EW_BLOCKS, 256>>>(db, dtp_w_l, dtp_b_l, dtb);
        scan_kernel<<<(2 * DI * NS) / 256, 256>>>(db, dtb, Xs, A_log_l, D_l, Y);
        gate_split_kernel<<<EW_BLOCKS, 256>>>(XZ, Y, ygH, ygL);
        mma_tn_bf16<<<dim3(BL / 128, DM / 128), 256, SMEM_TOT>>>(
            ygH, ygL, otwH + otw_off, otwL + otw_off, X, X, BL, DM, DI);
    }

    split_launch(lm_w, lmwH, lmwL, VOCAB * DM);
    rmsnorm_split_kernel<<<BL, 256>>>(X, xnH, xnL);
    mma_tn_bf16<<<dim3(BL / 128, VOCAB / 128), 256, SMEM_TOT>>>(
        xnH, xnL, lmwH, lmwL, nullptr, out, BL, VOCAB, DM);
}